// round 2
// baseline (speedup 1.0000x reference)
#include <cuda_runtime.h>
#include <math.h>

#define H    128
#define KNB  48
#define LSEQ 2048
#define NTOK_MAX 4096

// Scratch (static device globals — no allocation allowed)
__device__ float g_P1 [NTOK_MAX * H];
__device__ float g_P3 [NTOK_MAX * H];
__device__ float g_HV1[NTOK_MAX * H];
__device__ float g_P11[NTOK_MAX * H];
__device__ float g_P13[NTOK_MAX * H];

__device__ __forceinline__ float gelu_f(float x) {
    return 0.5f * x * (1.0f + erff(x * 0.70710678118654752f));
}

// acc[ROWS] += A[ROWS][K4*4] (smem, row-major) @ W[:, n]  (W row-major k x ldw)
template<int ROWS, int K4>
__device__ __forceinline__ void gemm_acc(float* acc, const float* A,
                                         const float* __restrict__ W,
                                         int n, int ldw) {
    const float4* A4 = reinterpret_cast<const float4*>(A);
    #pragma unroll 1
    for (int k4 = 0; k4 < K4; k4++) {
        const float* wp = W + (k4 * 4) * ldw + n;
        float w0 = wp[0];
        float w1 = wp[ldw];
        float w2 = wp[2 * ldw];
        float w3 = wp[3 * ldw];
        #pragma unroll
        for (int r = 0; r < ROWS; r++) {
            float4 a = A4[r * K4 + k4];   // warp-uniform address -> smem broadcast
            acc[r] = fmaf(a.x, w0, acc[r]);
            acc[r] = fmaf(a.y, w1, acc[r]);
            acc[r] = fmaf(a.z, w2, acc[r]);
            acc[r] = fmaf(a.w, w3, acc[r]);
        }
    }
}

// ---------------------------------------------------------------------------
// Kernel P: per-token precompute  P1 = hV @ W1a + b1,  P3 = hV @ W1c
// 32 tokens per block; W1a/W1c cached in smem (weights read once per block).
// ---------------------------------------------------------------------------
__global__ void __launch_bounds__(128) k_pre(const float* __restrict__ hV,
                                             const float* __restrict__ W1,
                                             const float* __restrict__ b1) {
    extern __shared__ float sm[];
    float* w1a  = sm;                // H*H
    float* w1c  = sm + H * H;        // H*H
    float* rows = sm + 2 * H * H;    // 32*H
    int tid = threadIdx.x;
    for (int i = tid; i < H * H; i += 128) {
        w1a[i] = W1[i];                   // rows 0..127   (center block)
        w1c[i] = W1[2 * H * H + i];       // rows 256..383 (neighbor block)
    }
    int t0 = blockIdx.x * 32;
    for (int i = tid; i < 32 * H; i += 128) rows[i] = hV[(size_t)t0 * H + i];
    __syncthreads();

    float bn = b1[tid];
    for (int r = 0; r < 32; r++) {
        float a1 = bn, a3 = 0.f;
        const float4* rv = reinterpret_cast<const float4*>(rows + r * H);
        #pragma unroll 8
        for (int k4 = 0; k4 < 32; k4++) {
            float4 v = rv[k4];
            int k = k4 * 4;
            a1 = fmaf(v.x, w1a[(k + 0) * H + tid], a1);
            a1 = fmaf(v.y, w1a[(k + 1) * H + tid], a1);
            a1 = fmaf(v.z, w1a[(k + 2) * H + tid], a1);
            a1 = fmaf(v.w, w1a[(k + 3) * H + tid], a1);
            a3 = fmaf(v.x, w1c[(k + 0) * H + tid], a3);
            a3 = fmaf(v.y, w1c[(k + 1) * H + tid], a3);
            a3 = fmaf(v.z, w1c[(k + 2) * H + tid], a3);
            a3 = fmaf(v.w, w1c[(k + 3) * H + tid], a3);
        }
        g_P1[(size_t)(t0 + r) * H + tid] = a1;
        g_P3[(size_t)(t0 + r) * H + tid] = a3;
    }
}

// ---------------------------------------------------------------------------
// Kernel A: node message MLP (48 edges per token), masked sum, residual + LN1
// One token per block; thread = output column; 48 edge rows in registers.
// ---------------------------------------------------------------------------
__global__ void __launch_bounds__(128, 3) k_node(
    const float* __restrict__ hV,  const float* __restrict__ hE,
    const int*   __restrict__ Eidx, const float* __restrict__ mattend,
    const float* __restrict__ W1,  const float* __restrict__ W2,
    const float* __restrict__ b2,  const float* __restrict__ W3,
    const float* __restrict__ b3,  const float* __restrict__ g1,
    const float* __restrict__ be1) {
    extern __shared__ float sm[];
    float* sE    = sm;                   // KNB*H : h_E rows
    float* sG    = sm + KNB * H;         // KNB*H : gathered P3, then layer2 out
    float* sBuf  = sm + 2 * KNB * H;     // KNB*H : layer1 out
    float* sP1   = sm + 3 * KNB * H;     // H
    float* sHV   = sP1 + H;              // H
    float* sMask = sHV + H;              // KNB
    float* sRed  = sMask + KNB;          // 8

    int tid = threadIdx.x;
    int t = blockIdx.x;
    int b = t / LSEQ;

    {   // load h_E tile
        const float4* src = reinterpret_cast<const float4*>(hE + (size_t)t * KNB * H);
        float4* dst = reinterpret_cast<float4*>(sE);
        for (int i = tid; i < KNB * H / 4; i += 128) dst[i] = src[i];
    }
    sP1[tid] = g_P1[(size_t)t * H + tid];
    sHV[tid] = hV [(size_t)t * H + tid];
    if (tid < KNB) sMask[tid] = mattend[(size_t)t * KNB + tid];
    {   // gather P3 rows of the 48 neighbors
        int warp = tid >> 5, lane = tid & 31;
        for (int r = warp; r < KNB; r += 4) {
            int idx = Eidx[(size_t)t * KNB + r];
            const float4* src = reinterpret_cast<const float4*>(g_P3 + (size_t)(b * LSEQ + idx) * H);
            reinterpret_cast<float4*>(sG + r * H)[lane] = src[lane];
        }
    }
    __syncthreads();

    float acc[KNB];
    // layer 1:  P1 + P3[gather] + hE @ W1b
    #pragma unroll
    for (int r = 0; r < KNB; r++) acc[r] = sP1[tid] + sG[r * H + tid];
    gemm_acc<KNB, 32>(acc, sE, W1 + H * H, tid, H);
    #pragma unroll
    for (int r = 0; r < KNB; r++) sBuf[r * H + tid] = gelu_f(acc[r]);
    __syncthreads();
    // layer 2
    {
        float bb = b2[tid];
        #pragma unroll
        for (int r = 0; r < KNB; r++) acc[r] = bb;
    }
    gemm_acc<KNB, 32>(acc, sBuf, W2, tid, H);
    #pragma unroll
    for (int r = 0; r < KNB; r++) sG[r * H + tid] = gelu_f(acc[r]);
    __syncthreads();
    // layer 3
    {
        float bb = b3[tid];
        #pragma unroll
        for (int r = 0; r < KNB; r++) acc[r] = bb;
    }
    gemm_acc<KNB, 32>(acc, sG, W3, tid, H);

    // masked sum over neighbors / 30, residual
    float dh = 0.f;
    #pragma unroll
    for (int r = 0; r < KNB; r++) dh = fmaf(sMask[r], acc[r], dh);
    float x = sHV[tid] + dh * (1.0f / 30.0f);

    // LayerNorm across the 128 threads
    float s = x, s2 = x * x;
    #pragma unroll
    for (int o = 16; o; o >>= 1) {
        s  += __shfl_xor_sync(0xffffffffu, s,  o);
        s2 += __shfl_xor_sync(0xffffffffu, s2, o);
    }
    if ((tid & 31) == 0) { sRed[tid >> 5] = s; sRed[4 + (tid >> 5)] = s2; }
    __syncthreads();
    s  = sRed[0] + sRed[1] + sRed[2] + sRed[3];
    s2 = sRed[4] + sRed[5] + sRed[6] + sRed[7];
    float m  = s * (1.f / H);
    float rs = rsqrtf(s2 * (1.f / H) - m * m + 1e-5f);
    g_HV1[(size_t)t * H + tid] = g1[tid] * (x - m) * rs + be1[tid];
}

// ---------------------------------------------------------------------------
// Kernel B: FFN (H->4H->H) + residual + LN2 + mask_V; also precompute
// P11 = hV2@W11a + b11 and P13 = hV2@W11c for the edge phase.
// 32 tokens per block.
// ---------------------------------------------------------------------------
__global__ void __launch_bounds__(128, 2) k_ffn(
    const float* __restrict__ maskV,
    const float* __restrict__ W_in,  const float* __restrict__ b_in,
    const float* __restrict__ W_out, const float* __restrict__ b_out,
    const float* __restrict__ g2,    const float* __restrict__ be2,
    const float* __restrict__ W11,   const float* __restrict__ b11,
    float* __restrict__ outV) {
    extern __shared__ float sm[];
    float* sX    = sm;               // 32*H
    float* sHid  = sm + 32 * H;      // 32*512
    float* sMask = sHid + 32 * 512;  // 32

    int tid = threadIdx.x;
    int t0 = blockIdx.x * 32;
    for (int i = tid; i < 32 * H; i += 128) sX[i] = g_HV1[(size_t)t0 * H + i];
    if (tid < 32) sMask[tid] = maskV[t0 + tid];
    __syncthreads();

    // hidden layer (512 cols, 4 chunks per thread)
    for (int c = 0; c < 4; c++) {
        int col = c * 128 + tid;
        float acc[32];
        float bi = b_in[col];
        #pragma unroll
        for (int r = 0; r < 32; r++) acc[r] = bi;
        gemm_acc<32, 32>(acc, sX, W_in, col, 512);
        #pragma unroll
        for (int r = 0; r < 32; r++) sHid[r * 512 + col] = gelu_f(acc[r]);
    }
    __syncthreads();

    // output layer + residual
    float acc[32];
    {
        float bo = b_out[tid];
        #pragma unroll
        for (int r = 0; r < 32; r++) acc[r] = bo;
    }
    gemm_acc<32, 128>(acc, sHid, W_out, tid, H);
    #pragma unroll
    for (int r = 0; r < 32; r++) acc[r] += sX[r * H + tid];
    __syncthreads();
    #pragma unroll
    for (int r = 0; r < 32; r++) sHid[r * H + tid] = acc[r];
    __syncthreads();

    // per-row LN + mask
    {
        int warp = tid >> 5, lane = tid & 31;
        for (int r = warp; r < 32; r += 4) {
            const float* row = sHid + r * H;
            float v[4] = { row[lane], row[lane + 32], row[lane + 64], row[lane + 96] };
            float s = v[0] + v[1] + v[2] + v[3];
            float s2 = v[0]*v[0] + v[1]*v[1] + v[2]*v[2] + v[3]*v[3];
            #pragma unroll
            for (int o = 16; o; o >>= 1) {
                s  += __shfl_xor_sync(0xffffffffu, s,  o);
                s2 += __shfl_xor_sync(0xffffffffu, s2, o);
            }
            float m  = s * (1.f / H);
            float rs = rsqrtf(s2 * (1.f / H) - m * m + 1e-5f);
            float mk = sMask[r];
            #pragma unroll
            for (int j = 0; j < 4; j++) {
                int n = lane + 32 * j;
                float y = mk * (g2[n] * (v[j] - m) * rs + be2[n]);
                outV[(size_t)(t0 + r) * H + n] = y;
                sX[r * H + n] = y;
            }
        }
    }
    __syncthreads();

    // P11 / P13 precompute for edge phase
    {
        float acc2[32];
        float bb = b11[tid];
        #pragma unroll
        for (int r = 0; r < 32; r++) acc2[r] = bb;
        gemm_acc<32, 32>(acc2, sX, W11, tid, H);
        #pragma unroll
        for (int r = 0; r < 32; r++) g_P11[(size_t)(t0 + r) * H + tid] = acc2[r];
        #pragma unroll
        for (int r = 0; r < 32; r++) acc2[r] = 0.f;
        gemm_acc<32, 32>(acc2, sX, W11 + 2 * H * H, tid, H);
        #pragma unroll
        for (int r = 0; r < 32; r++) g_P13[(size_t)(t0 + r) * H + tid] = acc2[r];
    }
}

// ---------------------------------------------------------------------------
// Kernel C: edge-update MLP + residual + per-edge LN3
// ---------------------------------------------------------------------------
__global__ void __launch_bounds__(128, 3) k_edge(
    const float* __restrict__ hE,  const int* __restrict__ Eidx,
    const float* __restrict__ W11, const float* __restrict__ W12,
    const float* __restrict__ b12, const float* __restrict__ W13,
    const float* __restrict__ b13, const float* __restrict__ g3,
    const float* __restrict__ be3, float* __restrict__ outE) {
    extern __shared__ float sm[];
    float* sE   = sm;                // KNB*H
    float* sG   = sm + KNB * H;      // KNB*H
    float* sBuf = sm + 2 * KNB * H;  // KNB*H
    float* sP   = sm + 3 * KNB * H;  // H

    int tid = threadIdx.x;
    int t = blockIdx.x;
    int b = t / LSEQ;

    {
        const float4* src = reinterpret_cast<const float4*>(hE + (size_t)t * KNB * H);
        float4* dst = reinterpret_cast<float4*>(sE);
        for (int i = tid; i < KNB * H / 4; i += 128) dst[i] = src[i];
    }
    sP[tid] = g_P11[(size_t)t * H + tid];
    {
        int warp = tid >> 5, lane = tid & 31;
        for (int r = warp; r < KNB; r += 4) {
            int idx = Eidx[(size_t)t * KNB + r];
            const float4* src = reinterpret_cast<const float4*>(g_P13 + (size_t)(b * LSEQ + idx) * H);
            reinterpret_cast<float4*>(sG + r * H)[lane] = src[lane];
        }
    }
    __syncthreads();

    float acc[KNB];
    #pragma unroll
    for (int r = 0; r < KNB; r++) acc[r] = sP[tid] + sG[r * H + tid];
    gemm_acc<KNB, 32>(acc, sE, W11 + H * H, tid, H);
    #pragma unroll
    for (int r = 0; r < KNB; r++) sBuf[r * H + tid] = gelu_f(acc[r]);
    __syncthreads();
    {
        float bb = b12[tid];
        #pragma unroll
        for (int r = 0; r < KNB; r++) acc[r] = bb;
    }
    gemm_acc<KNB, 32>(acc, sBuf, W12, tid, H);
    #pragma unroll
    for (int r = 0; r < KNB; r++) sG[r * H + tid] = gelu_f(acc[r]);
    __syncthreads();
    {
        float bb = b13[tid];
        #pragma unroll
        for (int r = 0; r < KNB; r++) acc[r] = bb;
    }
    gemm_acc<KNB, 32>(acc, sG, W13, tid, H);

    // x = h_E + msg
    #pragma unroll
    for (int r = 0; r < KNB; r++) sBuf[r * H + tid] = sE[r * H + tid] + acc[r];
    __syncthreads();

    // per-edge LN
    {
        int warp = tid >> 5, lane = tid & 31;
        for (int r = warp; r < KNB; r += 4) {
            const float* row = sBuf + r * H;
            float v[4] = { row[lane], row[lane + 32], row[lane + 64], row[lane + 96] };
            float s = v[0] + v[1] + v[2] + v[3];
            float s2 = v[0]*v[0] + v[1]*v[1] + v[2]*v[2] + v[3]*v[3];
            #pragma unroll
            for (int o = 16; o; o >>= 1) {
                s  += __shfl_xor_sync(0xffffffffu, s,  o);
                s2 += __shfl_xor_sync(0xffffffffu, s2, o);
            }
            float m  = s * (1.f / H);
            float rs = rsqrtf(s2 * (1.f / H) - m * m + 1e-5f);
            #pragma unroll
            for (int j = 0; j < 4; j++) {
                int n = lane + 32 * j;
                float y = g3[n] * (v[j] - m) * rs + be3[n];
                outE[(size_t)t * KNB * H + (size_t)r * H + n] = y;
            }
        }
    }
}

// ---------------------------------------------------------------------------
extern "C" void kernel_launch(void* const* d_in, const int* in_sizes, int n_in,
                              void* d_out, int out_size) {
    const float* hV    = (const float*)d_in[0];
    const float* hE    = (const float*)d_in[1];
    const int*   Eidx  = (const int*)  d_in[2];
    const float* maskV = (const float*)d_in[3];
    const float* matt  = (const float*)d_in[4];
    const float* W1    = (const float*)d_in[5];
    const float* b1    = (const float*)d_in[6];
    const float* W2    = (const float*)d_in[7];
    const float* b2    = (const float*)d_in[8];
    const float* W3    = (const float*)d_in[9];
    const float* b3    = (const float*)d_in[10];
    const float* W11   = (const float*)d_in[11];
    const float* b11   = (const float*)d_in[12];
    const float* W12   = (const float*)d_in[13];
    const float* b12   = (const float*)d_in[14];
    const float* W13   = (const float*)d_in[15];
    const float* b13   = (const float*)d_in[16];
    const float* g1    = (const float*)d_in[17];
    const float* be1   = (const float*)d_in[18];
    const float* g2    = (const float*)d_in[19];
    const float* be2   = (const float*)d_in[20];
    const float* g3    = (const float*)d_in[21];
    const float* be3   = (const float*)d_in[22];
    const float* W_in  = (const float*)d_in[23];
    const float* b_in  = (const float*)d_in[24];
    const float* W_out = (const float*)d_in[25];
    const float* b_out = (const float*)d_in[26];

    int ntok = in_sizes[3];   // B*L  (mask_V element count)

    size_t smemP = (size_t)(2 * H * H + 32 * H) * sizeof(float);
    size_t smemA = (size_t)(3 * KNB * H + 2 * H + KNB + 16) * sizeof(float);
    size_t smemB = (size_t)(32 * H + 32 * 512 + 64) * sizeof(float);
    size_t smemC = (size_t)(3 * KNB * H + H + 16) * sizeof(float);

    cudaFuncSetAttribute(k_pre,  cudaFuncAttributeMaxDynamicSharedMemorySize, (int)smemP);
    cudaFuncSetAttribute(k_node, cudaFuncAttributeMaxDynamicSharedMemorySize, (int)smemA);
    cudaFuncSetAttribute(k_ffn,  cudaFuncAttributeMaxDynamicSharedMemorySize, (int)smemB);
    cudaFuncSetAttribute(k_edge, cudaFuncAttributeMaxDynamicSharedMemorySize, (int)smemC);

    float* outV = (float*)d_out;
    float* outE = outV + (size_t)ntok * H;

    k_pre <<< ntok / 32, 128, smemP >>>(hV, W1, b1);
    k_node<<< ntok,      128, smemA >>>(hV, hE, Eidx, matt, W1, W2, b2, W3, b3, g1, be1);
    k_ffn <<< ntok / 32, 128, smemB >>>(maskV, W_in, b_in, W_out, b_out, g2, be2, W11, b11, outV);
    k_edge<<< ntok,      128, smemC >>>(hE, Eidx, W11, W12, b12, W13, b13, g3, be3, outE);
}

// round 5
// speedup vs baseline: 1.8294x; 1.8294x over previous
#include <cuda_runtime.h>
#include <cuda_bf16.h>
#include <math.h>
#include <cstdint>

#define H    128
#define KNB  48
#define LSEQ 2048
#define NTOK_MAX 4096

// ---------------- device scratch ----------------
__device__ float g_P1 [NTOK_MAX * H];
__device__ float g_P3 [NTOK_MAX * H];
__device__ float g_HV1[NTOK_MAX * H];
__device__ float g_P11[NTOK_MAX * H];
__device__ float g_P13[NTOK_MAX * H];
__device__ float g_dh [NTOK_MAX * H];
// 6 weight mats, transposed [n][k], hi then lo (each 16384 bf16)
__device__ __nv_bfloat16 g_W[6 * 32768];

__device__ __forceinline__ float gelu_f(float x) {
    return 0.5f * x * (1.0f + erff(x * 0.70710678118654752f));
}

__device__ __forceinline__ void split2(float a, float b, uint32_t& hi, uint32_t& lo) {
    __nv_bfloat162 h = __floats2bfloat162_rn(a, b);
    __nv_bfloat162 l = __floats2bfloat162_rn(a - __bfloat162float(h.x),
                                             b - __bfloat162float(h.y));
    hi = *reinterpret_cast<uint32_t*>(&h);
    lo = *reinterpret_cast<uint32_t*>(&l);
}

__device__ __forceinline__ void mma16816(float* c, const uint32_t* a,
                                         uint32_t b0, uint32_t b1) {
    asm volatile(
        "mma.sync.aligned.m16n8k16.row.col.f32.bf16.bf16.f32 "
        "{%0,%1,%2,%3}, {%4,%5,%6,%7}, {%8,%9}, {%0,%1,%2,%3};"
        : "+f"(c[0]), "+f"(c[1]), "+f"(c[2]), "+f"(c[3])
        : "r"(a[0]), "r"(a[1]), "r"(a[2]), "r"(a[3]), "r"(b0), "r"(b1));
}

// ---------------- smem layout (bytes) ----------------
// W: [hi 128x136][lo 128x136] bf16; A: same; stg: 128x130 f32 (EVEN stride!)
#define LDA    136
#define STG_LD 130
#define SLAB  34816          // 128*136*2
#define SM_W    0
#define SM_A    69632
#define SM_STG  139264       // 128*130*4 = 66560
#define SM_NBR  205824
#define SM_MASK 206336
#define SM_B2   206848
#define SM_B3   207360
#define SM_G    207872
#define SM_BE   208384
#define SM_PAR  208896       // 512 floats = 2048
#define SMEM_MLP 210944

// ---------------- weight prep: transpose + bf16 hi/lo split ----------------
__global__ void k_wprep(const float* W1b, const float* W2, const float* W3,
                        const float* W11b, const float* W12, const float* W13) {
    int id = blockIdx.x * 256 + threadIdx.x;    // 6*16384
    int m = id >> 14, e = id & 16383;
    int n = e >> 7, k = e & 127;
    const float* srcs[6] = {W1b, W2, W3, W11b, W12, W13};
    float v = srcs[m][k * H + n];
    __nv_bfloat16 h = __float2bfloat16(v);
    g_W[m * 32768 + e]         = h;
    g_W[m * 32768 + 16384 + e] = __float2bfloat16(v - __bfloat162float(h));
}

__device__ __forceinline__ void load_w(char* sm, int tid, int mat) {
    const uint4* src = reinterpret_cast<const uint4*>(g_W + (size_t)mat * 32768);
    #pragma unroll
    for (int it = 0; it < 16; it++) {
        int id = tid + it * 256;          // 0..4095 uint4
        int hl = id >> 11, j = id & 2047;
        int n = j >> 4, kc = (j & 15) << 3;
        *(uint4*)(sm + SM_W + hl * SLAB + (n * LDA + kc) * 2) = src[id];
    }
}

// 3-pass hi/lo GEMM: acc[8][8] += A(128x128) x W^T, this warp's 32x64 chunk
__device__ __forceinline__ void do_gemm(char* sm, float acc[8][8],
                                        int rowbase, int colh, int gid, int tig) {
    #pragma unroll 1
    for (int pass = 0; pass < 3; pass++) {
        const char* Ab = sm + SM_A + ((pass == 2) ? SLAB : 0);
        const char* Wb = sm + SM_W + ((pass == 1) ? SLAB : 0);
        #pragma unroll 1
        for (int ks = 0; ks < 8; ks++) {
            int kc = ks * 16 + 2 * tig;
            uint32_t aF[2][4];
            #pragma unroll
            for (int hh = 0; hh < 2; hh++) {
                int rb = rowbase + hh * 16 + gid;
                aF[hh][0] = *(const uint32_t*)(Ab + (rb * LDA + kc) * 2);
                aF[hh][1] = *(const uint32_t*)(Ab + ((rb + 8) * LDA + kc) * 2);
                aF[hh][2] = *(const uint32_t*)(Ab + (rb * LDA + kc + 8) * 2);
                aF[hh][3] = *(const uint32_t*)(Ab + ((rb + 8) * LDA + kc + 8) * 2);
            }
            #pragma unroll
            for (int nt = 0; nt < 8; nt++) {
                int n0 = colh * 64 + nt * 8 + gid;
                uint32_t b0 = *(const uint32_t*)(Wb + (n0 * LDA + kc) * 2);
                uint32_t b1 = *(const uint32_t*)(Wb + (n0 * LDA + kc + 8) * 2);
                mma16816(&acc[nt][0], aF[0], b0, b1);
                mma16816(&acc[nt][4], aF[1], b0, b1);
            }
        }
    }
}

// GELU(acc) -> A slabs (bf16 hi/lo), for next layer's input
__device__ __forceinline__ void epi_act(char* sm, float acc[8][8],
                                        int rowbase, int colh, int gid, int tig) {
    #pragma unroll
    for (int nt = 0; nt < 8; nt++) {
        int col = colh * 64 + nt * 8 + 2 * tig;
        #pragma unroll
        for (int q = 0; q < 4; q++) {
            int row = rowbase + q * 8 + gid;
            float v0 = gelu_f(acc[nt][q * 2]);
            float v1 = gelu_f(acc[nt][q * 2 + 1]);
            uint32_t hi, lo;
            split2(v0, v1, hi, lo);
            int boff = (row * LDA + col) * 2;
            *(uint32_t*)(sm + SM_A + boff)        = hi;
            *(uint32_t*)(sm + SM_A + SLAB + boff) = lo;
        }
    }
}

// ---------------- fused 3-layer MLP over one 128-row tile ----------------
// MODE 0: node messages -> masked per-token sums into g_dh (atomic)
// MODE 1: edge update -> +hE residual, row LN, write outE
template <int MODE>
__global__ void __launch_bounds__(256, 1) k_mlp(
    const float* __restrict__ hE, const int* __restrict__ Eidx,
    const float* __restrict__ bias2, const float* __restrict__ bias3,
    const float* __restrict__ lng, const float* __restrict__ lnb,
    const float* __restrict__ mattend, float* __restrict__ outE) {
    extern __shared__ char sm[];
    float* stg   = (float*)(sm + SM_STG);
    int*   snbr  = (int*)(sm + SM_NBR);
    float* smask = (float*)(sm + SM_MASK);
    float* sb2   = (float*)(sm + SM_B2);
    float* sb3   = (float*)(sm + SM_B3);
    float* sg    = (float*)(sm + SM_G);
    float* sbe   = (float*)(sm + SM_BE);
    float* spar  = (float*)(sm + SM_PAR);

    int tid = threadIdx.x, wid = tid >> 5, lane = tid & 31;
    int gid = lane >> 2, tig = lane & 3;
    int rowbase = (wid & 3) * 32;
    int colh = wid >> 2;
    int grow0 = blockIdx.x * 128;

    if (tid < 128) {
        int gr = grow0 + tid;
        int t = gr / KNB;
        snbr[tid] = (t / LSEQ) * LSEQ + Eidx[gr];
        smask[tid] = (MODE == 0) ? mattend[gr] : 0.f;
        sb2[tid] = bias2[tid]; sb3[tid] = bias3[tid];
        sg[tid] = lng[tid];    sbe[tid] = lnb[tid];
    }
    __syncthreads();

    // A <- split(hE tile), W <- layer0, stg <- P_center + P_nbr
    const float4* hE4 = reinterpret_cast<const float4*>(hE + (size_t)grow0 * H);
    #pragma unroll
    for (int it = 0; it < 16; it++) {
        int id = tid + it * 256;
        int rr = id >> 5, c4 = id & 31;
        float4 v = hE4[rr * 32 + c4];
        uint32_t h01, l01, h23, l23;
        split2(v.x, v.y, h01, l01);
        split2(v.z, v.w, h23, l23);
        int boff = (rr * LDA + c4 * 4) * 2;
        *(uint2*)(sm + SM_A + boff)        = make_uint2(h01, h23);
        *(uint2*)(sm + SM_A + SLAB + boff) = make_uint2(l01, l23);
    }
    load_w(sm, tid, MODE * 3 + 0);
    {
        const float* Padd = (MODE == 0) ? g_P1 : g_P11;
        const float* Pnbr = (MODE == 0) ? g_P3 : g_P13;
        #pragma unroll
        for (int it = 0; it < 16; it++) {
            int id = tid + it * 256;
            int rr = id >> 5, c4 = id & 31;
            int t = (grow0 + rr) / KNB;
            float4 a = ((const float4*)(Padd + (size_t)t * H))[c4];
            float4 b = ((const float4*)(Pnbr + (size_t)snbr[rr] * H))[c4];
            float* d = stg + rr * STG_LD + c4 * 4;
            d[0] = a.x + b.x; d[1] = a.y + b.y; d[2] = a.z + b.z; d[3] = a.w + b.w;
        }
    }
    __syncthreads();

    float acc[8][8];

    // ---- layer 1: init acc from stg (additive term), GEMM, GELU ----
    #pragma unroll
    for (int nt = 0; nt < 8; nt++) {
        int col = colh * 64 + nt * 8 + 2 * tig;
        #pragma unroll
        for (int q = 0; q < 4; q++) {
            int row = rowbase + q * 8 + gid;
            float2 c = *(const float2*)(stg + row * STG_LD + col);
            acc[nt][q * 2] = c.x; acc[nt][q * 2 + 1] = c.y;
        }
    }
    do_gemm(sm, acc, rowbase, colh, gid, tig);
    __syncthreads();
    epi_act(sm, acc, rowbase, colh, gid, tig);
    load_w(sm, tid, MODE * 3 + 1);
    __syncthreads();

    // ---- layer 2: init from b2 ----
    #pragma unroll
    for (int nt = 0; nt < 8; nt++) {
        int col = colh * 64 + nt * 8 + 2 * tig;
        float b0 = sb2[col], b1 = sb2[col + 1];
        #pragma unroll
        for (int q = 0; q < 4; q++) { acc[nt][q * 2] = b0; acc[nt][q * 2 + 1] = b1; }
    }
    do_gemm(sm, acc, rowbase, colh, gid, tig);
    __syncthreads();
    epi_act(sm, acc, rowbase, colh, gid, tig);
    load_w(sm, tid, MODE * 3 + 2);
    __syncthreads();

    // ---- layer 3: init from b3 ----
    #pragma unroll
    for (int nt = 0; nt < 8; nt++) {
        int col = colh * 64 + nt * 8 + 2 * tig;
        float b0 = sb3[col], b1 = sb3[col + 1];
        #pragma unroll
        for (int q = 0; q < 4; q++) { acc[nt][q * 2] = b0; acc[nt][q * 2 + 1] = b1; }
    }
    do_gemm(sm, acc, rowbase, colh, gid, tig);

    if (MODE == 0) {
        // masked values -> stg, then per-token column sums -> g_dh
        #pragma unroll
        for (int nt = 0; nt < 8; nt++) {
            int col = colh * 64 + nt * 8 + 2 * tig;
            #pragma unroll
            for (int q = 0; q < 4; q++) {
                int row = rowbase + q * 8 + gid;
                float mk = smask[row];
                float2 v = make_float2(mk * acc[nt][q * 2], mk * acc[nt][q * 2 + 1]);
                *(float2*)(stg + row * STG_LD + col) = v;
            }
        }
        __syncthreads();
        int c = tid & 127, half = tid >> 7;
        int t0 = grow0 / KNB;
        for (int tok = t0 + half; KNB * tok < grow0 + 128; tok += 2) {
            int r0 = KNB * tok - grow0, r1 = r0 + KNB;
            if (r0 < 0) r0 = 0;
            if (r1 > 128) r1 = 128;
            float s = 0.f;
            for (int rr = r0; rr < r1; rr++) s += stg[rr * STG_LD + c];
            atomicAdd(&g_dh[(size_t)tok * H + c], s);
        }
    } else {
        // residual + per-row LN -> outE
        float sA[4], sB[4];
        #pragma unroll
        for (int q = 0; q < 4; q++) { sA[q] = 0.f; sB[q] = 0.f; }
        #pragma unroll
        for (int nt = 0; nt < 8; nt++) {
            int col = colh * 64 + nt * 8 + 2 * tig;
            #pragma unroll
            for (int q = 0; q < 4; q++) {
                int row = rowbase + q * 8 + gid;
                float2 res = *(const float2*)(hE + (size_t)(grow0 + row) * H + col);
                float x0 = acc[nt][q * 2]     + res.x;
                float x1 = acc[nt][q * 2 + 1] + res.y;
                acc[nt][q * 2] = x0; acc[nt][q * 2 + 1] = x1;
                sA[q] += x0 + x1;
                sB[q] += x0 * x0 + x1 * x1;
            }
        }
        #pragma unroll
        for (int q = 0; q < 4; q++) {
            sA[q] += __shfl_xor_sync(0xffffffffu, sA[q], 1);
            sA[q] += __shfl_xor_sync(0xffffffffu, sA[q], 2);
            sB[q] += __shfl_xor_sync(0xffffffffu, sB[q], 1);
            sB[q] += __shfl_xor_sync(0xffffffffu, sB[q], 2);
        }
        if (tig == 0) {
            #pragma unroll
            for (int q = 0; q < 4; q++) {
                int row = rowbase + q * 8 + gid;
                spar[colh * 128 + row]       = sA[q];
                spar[256 + colh * 128 + row] = sB[q];
            }
        }
        __syncthreads();
        if (tid < 128) {
            float ss  = spar[tid] + spar[128 + tid];
            float ss2 = spar[256 + tid] + spar[384 + tid];
            float m = ss * (1.f / H);
            spar[tid] = m;
            spar[128 + tid] = rsqrtf(ss2 * (1.f / H) - m * m + 1e-5f);
        }
        __syncthreads();
        #pragma unroll
        for (int nt = 0; nt < 8; nt++) {
            int col = colh * 64 + nt * 8 + 2 * tig;
            float g0 = sg[col], g1 = sg[col + 1];
            float e0 = sbe[col], e1 = sbe[col + 1];
            #pragma unroll
            for (int q = 0; q < 4; q++) {
                int row = rowbase + q * 8 + gid;
                float m = spar[row], rs = spar[128 + row];
                float2 y;
                y.x = g0 * (acc[nt][q * 2]     - m) * rs + e0;
                y.y = g1 * (acc[nt][q * 2 + 1] - m) * rs + e1;
                *(float2*)(outE + (size_t)(grow0 + row) * H + col) = y;
            }
        }
    }
}

// ---------------- node LN after dh accumulation ----------------
__global__ void __launch_bounds__(128) k_ln1(const float* __restrict__ hV,
                                             const float* __restrict__ g1,
                                             const float* __restrict__ be1) {
    __shared__ float red[8];
    int tid = threadIdx.x, t = blockIdx.x;
    float x = hV[(size_t)t * H + tid] + g_dh[(size_t)t * H + tid] * (1.f / 30.f);
    float s = x, s2 = x * x;
    #pragma unroll
    for (int o = 16; o; o >>= 1) {
        s  += __shfl_xor_sync(0xffffffffu, s,  o);
        s2 += __shfl_xor_sync(0xffffffffu, s2, o);
    }
    if ((tid & 31) == 0) { red[tid >> 5] = s; red[4 + (tid >> 5)] = s2; }
    __syncthreads();
    s  = red[0] + red[1] + red[2] + red[3];
    s2 = red[4] + red[5] + red[6] + red[7];
    float m = s * (1.f / H);
    float rs = rsqrtf(s2 * (1.f / H) - m * m + 1e-5f);
    g_HV1[(size_t)t * H + tid] = g1[tid] * (x - m) * rs + be1[tid];
}

// ---------------- fp32 helpers for pre / ffn ----------------
template<int ROWS, int K4>
__device__ __forceinline__ void gemm_acc(float* acc, const float* A,
                                         const float* __restrict__ W,
                                         int n, int ldw) {
    const float4* A4 = reinterpret_cast<const float4*>(A);
    #pragma unroll 1
    for (int k4 = 0; k4 < K4; k4++) {
        const float* wp = W + (k4 * 4) * ldw + n;
        float w0 = wp[0], w1 = wp[ldw], w2 = wp[2 * ldw], w3 = wp[3 * ldw];
        #pragma unroll
        for (int rr = 0; rr < ROWS; rr++) {
            float4 a = A4[rr * K4 + k4];
            acc[rr] = fmaf(a.x, w0, acc[rr]);
            acc[rr] = fmaf(a.y, w1, acc[rr]);
            acc[rr] = fmaf(a.z, w2, acc[rr]);
            acc[rr] = fmaf(a.w, w3, acc[rr]);
        }
    }
}

__global__ void __launch_bounds__(128) k_pre(const float* __restrict__ hV,
                                             const float* __restrict__ W1,
                                             const float* __restrict__ b1,
                                             int ntok) {
    for (int i = blockIdx.x * 128 + threadIdx.x; i < ntok * H; i += gridDim.x * 128)
        g_dh[i] = 0.f;
    extern __shared__ float smf[];
    float* w1a = smf;
    float* w1c = smf + H * H;
    float* rows = smf + 2 * H * H;
    int tid = threadIdx.x;
    for (int i = tid; i < H * H; i += 128) {
        w1a[i] = W1[i];
        w1c[i] = W1[2 * H * H + i];
    }
    int t0 = blockIdx.x * 32;
    for (int i = tid; i < 32 * H; i += 128) rows[i] = hV[(size_t)t0 * H + i];
    __syncthreads();
    float bn = b1[tid];
    for (int rr = 0; rr < 32; rr++) {
        float a1 = bn, a3 = 0.f;
        const float4* rv = reinterpret_cast<const float4*>(rows + rr * H);
        #pragma unroll 8
        for (int k4 = 0; k4 < 32; k4++) {
            float4 v = rv[k4];
            int k = k4 * 4;
            a1 = fmaf(v.x, w1a[(k+0)*H+tid], a1); a1 = fmaf(v.y, w1a[(k+1)*H+tid], a1);
            a1 = fmaf(v.z, w1a[(k+2)*H+tid], a1); a1 = fmaf(v.w, w1a[(k+3)*H+tid], a1);
            a3 = fmaf(v.x, w1c[(k+0)*H+tid], a3); a3 = fmaf(v.y, w1c[(k+1)*H+tid], a3);
            a3 = fmaf(v.z, w1c[(k+2)*H+tid], a3); a3 = fmaf(v.w, w1c[(k+3)*H+tid], a3);
        }
        g_P1[(size_t)(t0+rr)*H+tid] = a1;
        g_P3[(size_t)(t0+rr)*H+tid] = a3;
    }
}

__global__ void __launch_bounds__(128, 2) k_ffn(
    const float* __restrict__ maskV,
    const float* __restrict__ W_in,  const float* __restrict__ b_in,
    const float* __restrict__ W_out, const float* __restrict__ b_out,
    const float* __restrict__ g2,    const float* __restrict__ be2,
    const float* __restrict__ W11,   const float* __restrict__ b11,
    float* __restrict__ outV) {
    extern __shared__ float smf[];
    float* sX   = smf;
    float* sHid = smf + 32 * H;
    float* sMk  = sHid + 32 * 512;
    int tid = threadIdx.x;
    int t0 = blockIdx.x * 32;
    for (int i = tid; i < 32 * H; i += 128) sX[i] = g_HV1[(size_t)t0 * H + i];
    if (tid < 32) sMk[tid] = maskV[t0 + tid];
    __syncthreads();
    for (int cc = 0; cc < 4; cc++) {
        int col = cc * 128 + tid;
        float acc[32];
        float bi = b_in[col];
        #pragma unroll
        for (int rr = 0; rr < 32; rr++) acc[rr] = bi;
        gemm_acc<32, 32>(acc, sX, W_in, col, 512);
        #pragma unroll
        for (int rr = 0; rr < 32; rr++) sHid[rr * 512 + col] = gelu_f(acc[rr]);
    }
    __syncthreads();
    float acc[32];
    {
        float bo = b_out[tid];
        #pragma unroll
        for (int rr = 0; rr < 32; rr++) acc[rr] = bo;
    }
    gemm_acc<32, 128>(acc, sHid, W_out, tid, H);
    #pragma unroll
    for (int rr = 0; rr < 32; rr++) acc[rr] += sX[rr * H + tid];
    __syncthreads();
    #pragma unroll
    for (int rr = 0; rr < 32; rr++) sHid[rr * H + tid] = acc[rr];
    __syncthreads();
    {
        int warp = tid >> 5, lane = tid & 31;
        for (int rr = warp; rr < 32; rr += 4) {
            const float* row = sHid + rr * H;
            float v[4] = { row[lane], row[lane+32], row[lane+64], row[lane+96] };
            float s = v[0]+v[1]+v[2]+v[3];
            float s2 = v[0]*v[0]+v[1]*v[1]+v[2]*v[2]+v[3]*v[3];
            #pragma unroll
            for (int o = 16; o; o >>= 1) {
                s  += __shfl_xor_sync(0xffffffffu, s,  o);
                s2 += __shfl_xor_sync(0xffffffffu, s2, o);
            }
            float m = s * (1.f/H);
            float rs = rsqrtf(s2 * (1.f/H) - m*m + 1e-5f);
            float mk = sMk[rr];
            #pragma unroll
            for (int j = 0; j < 4; j++) {
                int n = lane + 32*j;
                float y = mk * (g2[n]*(v[j]-m)*rs + be2[n]);
                outV[(size_t)(t0+rr)*H + n] = y;
                sX[rr*H + n] = y;
            }
        }
    }
    __syncthreads();
    {
        float acc2[32];
        float bb = b11[tid];
        #pragma unroll
        for (int rr = 0; rr < 32; rr++) acc2[rr] = bb;
        gemm_acc<32, 32>(acc2, sX, W11, tid, H);
        #pragma unroll
        for (int rr = 0; rr < 32; rr++) g_P11[(size_t)(t0+rr)*H+tid] = acc2[rr];
        #pragma unroll
        for (int rr = 0; rr < 32; rr++) acc2[rr] = 0.f;
        gemm_acc<32, 32>(acc2, sX, W11 + 2*H*H, tid, H);
        #pragma unroll
        for (int rr = 0; rr < 32; rr++) g_P13[(size_t)(t0+rr)*H+tid] = acc2[rr];
    }
}

// ---------------------------------------------------------------------------
extern "C" void kernel_launch(void* const* d_in, const int* in_sizes, int n_in,
                              void* d_out, int out_size) {
    const float* hV    = (const float*)d_in[0];
    const float* hE    = (const float*)d_in[1];
    const int*   Eidx  = (const int*)  d_in[2];
    const float* maskV = (const float*)d_in[3];
    const float* matt  = (const float*)d_in[4];
    const float* W1    = (const float*)d_in[5];
    const float* b1    = (const float*)d_in[6];
    const float* W2    = (const float*)d_in[7];
    const float* b2    = (const float*)d_in[8];
    const float* W3    = (const float*)d_in[9];
    const float* b3    = (const float*)d_in[10];
    const float* W11   = (const float*)d_in[11];
    const float* b11   = (const float*)d_in[12];
    const float* W12   = (const float*)d_in[13];
    const float* b12   = (const float*)d_in[14];
    const float* W13   = (const float*)d_in[15];
    const float* b13   = (const float*)d_in[16];
    const float* g1    = (const float*)d_in[17];
    const float* be1   = (const float*)d_in[18];
    const float* g2    = (const float*)d_in[19];
    const float* be2   = (const float*)d_in[20];
    const float* g3    = (const float*)d_in[21];
    const float* be3   = (const float*)d_in[22];
    const float* W_in  = (const float*)d_in[23];
    const float* b_in  = (const float*)d_in[24];
    const float* W_out = (const float*)d_in[25];
    const float* b_out = (const float*)d_in[26];

    int ntok = in_sizes[3];

    size_t smemP = (size_t)(2 * H * H + 32 * H) * sizeof(float);
    size_t smemB = (size_t)(32 * H + 32 * 512 + 64) * sizeof(float);

    cudaFuncSetAttribute(k_pre,    cudaFuncAttributeMaxDynamicSharedMemorySize, (int)smemP);
    cudaFuncSetAttribute(k_ffn,    cudaFuncAttributeMaxDynamicSharedMemorySize, (int)smemB);
    cudaFuncSetAttribute(k_mlp<0>, cudaFuncAttributeMaxDynamicSharedMemorySize, SMEM_MLP);
    cudaFuncSetAttribute(k_mlp<1>, cudaFuncAttributeMaxDynamicSharedMemorySize, SMEM_MLP);

    float* outV = (float*)d_out;
    float* outE = outV + (size_t)ntok * H;
    int ntile = ntok * KNB / 128;

    k_wprep<<< 6 * 16384 / 256, 256 >>>(W1 + H * H, W2, W3, W11 + H * H, W12, W13);
    k_pre  <<< ntok / 32, 128, smemP >>>(hV, W1, b1, ntok);
    k_mlp<0><<< ntile, 256, SMEM_MLP >>>(hE, Eidx, b2, b3, g1, be1, matt, outE);
    k_ln1  <<< ntok, 128 >>>(hV, g1, be1);
    k_ffn  <<< ntok / 32, 128, smemB >>>(maskV, W_in, b_in, W_out, b_out, g2, be2, W11, b11, outV);
    k_mlp<1><<< ntile, 256, SMEM_MLP >>>(hE, Eidx, b12, b13, g3, be3, matt, outE);
}

// round 6
// speedup vs baseline: 2.0041x; 1.0955x over previous
#include <cuda_runtime.h>
#include <cuda_bf16.h>
#include <math.h>
#include <cstdint>

#define H    128
#define KNB  48
#define LSEQ 2048
#define NTOK_MAX 4096

// ---------------- device scratch ----------------
__device__ float g_P1 [NTOK_MAX * H];
__device__ float g_P3 [NTOK_MAX * H];
__device__ float g_HV1[NTOK_MAX * H];
__device__ float g_P11[NTOK_MAX * H];
__device__ float g_P13[NTOK_MAX * H];
__device__ float g_dh [NTOK_MAX * H];
// 6 weight mats, transposed [n][k], hi then lo (each 16384 bf16)
__device__ __nv_bfloat16 g_W[6 * 32768];

__device__ __forceinline__ float gelu_f(float x) {
    return 0.5f * x * (1.0f + erff(x * 0.70710678118654752f));
}

__device__ __forceinline__ void split2(float a, float b, uint32_t& hi, uint32_t& lo) {
    __nv_bfloat162 h = __floats2bfloat162_rn(a, b);
    __nv_bfloat162 l = __floats2bfloat162_rn(a - __bfloat162float(h.x),
                                             b - __bfloat162float(h.y));
    hi = *reinterpret_cast<uint32_t*>(&h);
    lo = *reinterpret_cast<uint32_t*>(&l);
}

__device__ __forceinline__ uint32_t smem_u32(const void* p) {
    uint32_t a;
    asm("{ .reg .u64 t; cvta.to.shared.u64 t, %1; cvt.u32.u64 %0, t; }" : "=r"(a) : "l"(p));
    return a;
}

__device__ __forceinline__ void mma16816(float* c, const uint32_t* a,
                                         uint32_t b0, uint32_t b1) {
    asm volatile(
        "mma.sync.aligned.m16n8k16.row.col.f32.bf16.bf16.f32 "
        "{%0,%1,%2,%3}, {%4,%5,%6,%7}, {%8,%9}, {%0,%1,%2,%3};"
        : "+f"(c[0]), "+f"(c[1]), "+f"(c[2]), "+f"(c[3])
        : "r"(a[0]), "r"(a[1]), "r"(a[2]), "r"(a[3]), "r"(b0), "r"(b1));
}

#define LDSM4(r0, r1, r2, r3, addr) \
    asm volatile("ldmatrix.sync.aligned.m8n8.x4.shared.b16 {%0,%1,%2,%3}, [%4];" \
                 : "=r"(r0), "=r"(r1), "=r"(r2), "=r"(r3) : "r"(addr))

// ---------------- smem layout (bytes) ----------------
// W: [hi 128x136][lo 128x136] bf16; A: same; stg: 128x130 f32 (even stride)
#define LDA    136
#define STG_LD 130
#define SLAB  34816          // 128*136*2
#define SM_W    0
#define SM_A    69632
#define SM_STG  139264       // 128*130*4 = 66560
#define SM_NBR  205824
#define SM_MASK 206336
#define SM_B2   206848
#define SM_B3   207360
#define SM_G    207872
#define SM_BE   208384
#define SM_PAR  208896       // 512 floats = 2048
#define SMEM_MLP 210944

// ---------------- weight prep: transpose + bf16 hi/lo split ----------------
__global__ void k_wprep(const float* W1b, const float* W2, const float* W3,
                        const float* W11b, const float* W12, const float* W13) {
    int id = blockIdx.x * 256 + threadIdx.x;    // 6*16384
    int m = id >> 14, e = id & 16383;
    int n = e >> 7, k = e & 127;
    const float* srcs[6] = {W1b, W2, W3, W11b, W12, W13};
    float v = srcs[m][k * H + n];
    __nv_bfloat16 h = __float2bfloat16(v);
    g_W[m * 32768 + e]         = h;
    g_W[m * 32768 + 16384 + e] = __float2bfloat16(v - __bfloat162float(h));
}

__device__ __forceinline__ void load_w(char* sm, int tid, int mat) {
    const uint4* src = reinterpret_cast<const uint4*>(g_W + (size_t)mat * 32768);
    #pragma unroll
    for (int it = 0; it < 16; it++) {
        int id = tid + it * 256;          // 0..4095 uint4
        int hl = id >> 11, j = id & 2047;
        int n = j >> 4, kc = (j & 15) << 3;
        *(uint4*)(sm + SM_W + hl * SLAB + (n * LDA + kc) * 2) = src[id];
    }
}

// 3-pass hi/lo GEMM via ldmatrix: acc[8][8] += A(128x128) x W^T (warp: 32x64)
__device__ __forceinline__ void do_gemm(uint32_t smb, float acc[8][8],
                                        int rowbase, int colh, int lane) {
    int arow = rowbase + (lane & 15);
    int acol = (lane >> 4) << 3;
    uint32_t aOff = smb + SM_A + (uint32_t)((arow * LDA + acol) * 2);
    int nrow = colh * 64 + (lane & 7) + ((lane >> 4) << 3);
    int bcol = ((lane >> 3) & 1) << 3;
    uint32_t bOff = smb + SM_W + (uint32_t)((nrow * LDA + bcol) * 2);
    #pragma unroll 1
    for (int pass = 0; pass < 3; pass++) {
        uint32_t aB = aOff + ((pass == 2) ? SLAB : 0);
        uint32_t bB = bOff + ((pass == 1) ? SLAB : 0);
        #pragma unroll 1
        for (int ks = 0; ks < 8; ks++) {
            uint32_t a0[4], a1[4];
            LDSM4(a0[0], a0[1], a0[2], a0[3], aB + ks * 32);
            LDSM4(a1[0], a1[1], a1[2], a1[3], aB + 16 * LDA * 2 + ks * 32);
            #pragma unroll
            for (int ntp = 0; ntp < 4; ntp++) {
                uint32_t b0, b1, b2, b3;
                LDSM4(b0, b1, b2, b3, bB + ntp * 16 * LDA * 2 + ks * 32);
                mma16816(&acc[2 * ntp][0],     a0, b0, b1);
                mma16816(&acc[2 * ntp][4],     a1, b0, b1);
                mma16816(&acc[2 * ntp + 1][0], a0, b2, b3);
                mma16816(&acc[2 * ntp + 1][4], a1, b2, b3);
            }
        }
    }
}

// GELU(acc) -> A slabs (bf16 hi/lo), for next layer's input
__device__ __forceinline__ void epi_act(char* sm, float acc[8][8],
                                        int rowbase, int colh, int gid, int tig) {
    #pragma unroll
    for (int nt = 0; nt < 8; nt++) {
        int col = colh * 64 + nt * 8 + 2 * tig;
        #pragma unroll
        for (int q = 0; q < 4; q++) {
            int row = rowbase + q * 8 + gid;
            float v0 = gelu_f(acc[nt][q * 2]);
            float v1 = gelu_f(acc[nt][q * 2 + 1]);
            uint32_t hi, lo;
            split2(v0, v1, hi, lo);
            int boff = (row * LDA + col) * 2;
            *(uint32_t*)(sm + SM_A + boff)        = hi;
            *(uint32_t*)(sm + SM_A + SLAB + boff) = lo;
        }
    }
}

// ---------------- fused 3-layer MLP over one 128-row tile ----------------
// MODE 0: node messages -> masked per-token sums into g_dh (atomic)
// MODE 1: edge update -> +hE residual, row LN, write outE
template <int MODE>
__global__ void __launch_bounds__(256, 1) k_mlp(
    const float* __restrict__ hE, const int* __restrict__ Eidx,
    const float* __restrict__ bias2, const float* __restrict__ bias3,
    const float* __restrict__ lng, const float* __restrict__ lnb,
    const float* __restrict__ mattend, float* __restrict__ outE) {
    extern __shared__ char sm[];
    float* stg   = (float*)(sm + SM_STG);
    int*   snbr  = (int*)(sm + SM_NBR);
    float* smask = (float*)(sm + SM_MASK);
    float* sb2   = (float*)(sm + SM_B2);
    float* sb3   = (float*)(sm + SM_B3);
    float* sg    = (float*)(sm + SM_G);
    float* sbe   = (float*)(sm + SM_BE);
    float* spar  = (float*)(sm + SM_PAR);

    int tid = threadIdx.x, wid = tid >> 5, lane = tid & 31;
    int gid = lane >> 2, tig = lane & 3;
    int rowbase = (wid & 3) * 32;
    int colh = wid >> 2;
    int grow0 = blockIdx.x * 128;
    uint32_t smb = smem_u32(sm);

    if (tid < 128) {
        int gr = grow0 + tid;
        int t = gr / KNB;
        snbr[tid] = (t / LSEQ) * LSEQ + Eidx[gr];
        smask[tid] = (MODE == 0) ? mattend[gr] : 0.f;
        sb2[tid] = bias2[tid]; sb3[tid] = bias3[tid];
        sg[tid] = lng[tid];    sbe[tid] = lnb[tid];
    }
    __syncthreads();

    // A <- split(hE tile), W <- layer0, stg <- P_center + P_nbr
    const float4* hE4 = reinterpret_cast<const float4*>(hE + (size_t)grow0 * H);
    #pragma unroll
    for (int it = 0; it < 16; it++) {
        int id = tid + it * 256;
        int rr = id >> 5, c4 = id & 31;
        float4 v = hE4[rr * 32 + c4];
        uint32_t h01, l01, h23, l23;
        split2(v.x, v.y, h01, l01);
        split2(v.z, v.w, h23, l23);
        int boff = (rr * LDA + c4 * 4) * 2;
        *(uint2*)(sm + SM_A + boff)        = make_uint2(h01, h23);
        *(uint2*)(sm + SM_A + SLAB + boff) = make_uint2(l01, l23);
    }
    load_w(sm, tid, MODE * 3 + 0);
    {
        const float* Padd = (MODE == 0) ? g_P1 : g_P11;
        const float* Pnbr = (MODE == 0) ? g_P3 : g_P13;
        #pragma unroll
        for (int it = 0; it < 16; it++) {
            int id = tid + it * 256;
            int rr = id >> 5, c4 = id & 31;
            int t = (grow0 + rr) / KNB;
            float4 a = ((const float4*)(Padd + (size_t)t * H))[c4];
            float4 b = ((const float4*)(Pnbr + (size_t)snbr[rr] * H))[c4];
            float* d = stg + rr * STG_LD + c4 * 4;
            d[0] = a.x + b.x; d[1] = a.y + b.y; d[2] = a.z + b.z; d[3] = a.w + b.w;
        }
    }
    __syncthreads();

    float acc[8][8];

    // ---- layer 1: init acc from stg (additive term), GEMM, GELU ----
    #pragma unroll
    for (int nt = 0; nt < 8; nt++) {
        int col = colh * 64 + nt * 8 + 2 * tig;
        #pragma unroll
        for (int q = 0; q < 4; q++) {
            int row = rowbase + q * 8 + gid;
            float2 c = *(const float2*)(stg + row * STG_LD + col);
            acc[nt][q * 2] = c.x; acc[nt][q * 2 + 1] = c.y;
        }
    }
    do_gemm(smb, acc, rowbase, colh, lane);
    __syncthreads();
    epi_act(sm, acc, rowbase, colh, gid, tig);
    load_w(sm, tid, MODE * 3 + 1);
    __syncthreads();

    // ---- layer 2: init from b2 ----
    #pragma unroll
    for (int nt = 0; nt < 8; nt++) {
        int col = colh * 64 + nt * 8 + 2 * tig;
        float b0 = sb2[col], b1 = sb2[col + 1];
        #pragma unroll
        for (int q = 0; q < 4; q++) { acc[nt][q * 2] = b0; acc[nt][q * 2 + 1] = b1; }
    }
    do_gemm(smb, acc, rowbase, colh, lane);
    __syncthreads();
    epi_act(sm, acc, rowbase, colh, gid, tig);
    load_w(sm, tid, MODE * 3 + 2);
    __syncthreads();

    // ---- layer 3: init from b3 ----
    #pragma unroll
    for (int nt = 0; nt < 8; nt++) {
        int col = colh * 64 + nt * 8 + 2 * tig;
        float b0 = sb3[col], b1 = sb3[col + 1];
        #pragma unroll
        for (int q = 0; q < 4; q++) { acc[nt][q * 2] = b0; acc[nt][q * 2 + 1] = b1; }
    }
    do_gemm(smb, acc, rowbase, colh, lane);

    if (MODE == 0) {
        // masked values -> stg, then per-token column sums -> g_dh
        #pragma unroll
        for (int nt = 0; nt < 8; nt++) {
            int col = colh * 64 + nt * 8 + 2 * tig;
            #pragma unroll
            for (int q = 0; q < 4; q++) {
                int row = rowbase + q * 8 + gid;
                float mk = smask[row];
                float2 v = make_float2(mk * acc[nt][q * 2], mk * acc[nt][q * 2 + 1]);
                *(float2*)(stg + row * STG_LD + col) = v;
            }
        }
        __syncthreads();
        int c = tid & 127, half = tid >> 7;
        int t0 = grow0 / KNB;
        for (int tok = t0 + half; KNB * tok < grow0 + 128; tok += 2) {
            int r0 = KNB * tok - grow0, r1 = r0 + KNB;
            if (r0 < 0) r0 = 0;
            if (r1 > 128) r1 = 128;
            float s = 0.f;
            for (int rr = r0; rr < r1; rr++) s += stg[rr * STG_LD + c];
            atomicAdd(&g_dh[(size_t)tok * H + c], s);
        }
    } else {
        // residual + per-row LN -> outE
        float sA[4], sB[4];
        #pragma unroll
        for (int q = 0; q < 4; q++) { sA[q] = 0.f; sB[q] = 0.f; }
        #pragma unroll
        for (int nt = 0; nt < 8; nt++) {
            int col = colh * 64 + nt * 8 + 2 * tig;
            #pragma unroll
            for (int q = 0; q < 4; q++) {
                int row = rowbase + q * 8 + gid;
                float2 res = *(const float2*)(hE + (size_t)(grow0 + row) * H + col);
                float x0 = acc[nt][q * 2]     + res.x;
                float x1 = acc[nt][q * 2 + 1] + res.y;
                acc[nt][q * 2] = x0; acc[nt][q * 2 + 1] = x1;
                sA[q] += x0 + x1;
                sB[q] += x0 * x0 + x1 * x1;
            }
        }
        #pragma unroll
        for (int q = 0; q < 4; q++) {
            sA[q] += __shfl_xor_sync(0xffffffffu, sA[q], 1);
            sA[q] += __shfl_xor_sync(0xffffffffu, sA[q], 2);
            sB[q] += __shfl_xor_sync(0xffffffffu, sB[q], 1);
            sB[q] += __shfl_xor_sync(0xffffffffu, sB[q], 2);
        }
        if (tig == 0) {
            #pragma unroll
            for (int q = 0; q < 4; q++) {
                int row = rowbase + q * 8 + gid;
                spar[colh * 128 + row]       = sA[q];
                spar[256 + colh * 128 + row] = sB[q];
            }
        }
        __syncthreads();
        if (tid < 128) {
            float ss  = spar[tid] + spar[128 + tid];
            float ss2 = spar[256 + tid] + spar[384 + tid];
            float m = ss * (1.f / H);
            spar[tid] = m;
            spar[128 + tid] = rsqrtf(ss2 * (1.f / H) - m * m + 1e-5f);
        }
        __syncthreads();
        #pragma unroll
        for (int nt = 0; nt < 8; nt++) {
            int col = colh * 64 + nt * 8 + 2 * tig;
            float g0 = sg[col], g1 = sg[col + 1];
            float e0 = sbe[col], e1 = sbe[col + 1];
            #pragma unroll
            for (int q = 0; q < 4; q++) {
                int row = rowbase + q * 8 + gid;
                float m = spar[row], rs = spar[128 + row];
                float2 y;
                y.x = g0 * (acc[nt][q * 2]     - m) * rs + e0;
                y.y = g1 * (acc[nt][q * 2 + 1] - m) * rs + e1;
                *(float2*)(outE + (size_t)(grow0 + row) * H + col) = y;
            }
        }
    }
}

// ---------------- node LN after dh accumulation ----------------
__global__ void __launch_bounds__(128) k_ln1(const float* __restrict__ hV,
                                             const float* __restrict__ g1,
                                             const float* __restrict__ be1) {
    __shared__ float red[8];
    int tid = threadIdx.x, t = blockIdx.x;
    float x = hV[(size_t)t * H + tid] + g_dh[(size_t)t * H + tid] * (1.f / 30.f);
    float s = x, s2 = x * x;
    #pragma unroll
    for (int o = 16; o; o >>= 1) {
        s  += __shfl_xor_sync(0xffffffffu, s,  o);
        s2 += __shfl_xor_sync(0xffffffffu, s2, o);
    }
    if ((tid & 31) == 0) { red[tid >> 5] = s; red[4 + (tid >> 5)] = s2; }
    __syncthreads();
    s  = red[0] + red[1] + red[2] + red[3];
    s2 = red[4] + red[5] + red[6] + red[7];
    float m = s * (1.f / H);
    float rs = rsqrtf(s2 * (1.f / H) - m * m + 1e-5f);
    g_HV1[(size_t)t * H + tid] = g1[tid] * (x - m) * rs + be1[tid];
}

// ---------------- fp32 helpers for pre / ffn ----------------
template<int ROWS, int K4>
__device__ __forceinline__ void gemm_acc(float* acc, const float* A,
                                         const float* __restrict__ W,
                                         int n, int ldw) {
    const float4* A4 = reinterpret_cast<const float4*>(A);
    #pragma unroll 1
    for (int k4 = 0; k4 < K4; k4++) {
        const float* wp = W + (k4 * 4) * ldw + n;
        float w0 = wp[0], w1 = wp[ldw], w2 = wp[2 * ldw], w3 = wp[3 * ldw];
        #pragma unroll
        for (int rr = 0; rr < ROWS; rr++) {
            float4 a = A4[rr * K4 + k4];
            acc[rr] = fmaf(a.x, w0, acc[rr]);
            acc[rr] = fmaf(a.y, w1, acc[rr]);
            acc[rr] = fmaf(a.z, w2, acc[rr]);
            acc[rr] = fmaf(a.w, w3, acc[rr]);
        }
    }
}

__global__ void __launch_bounds__(128) k_pre(const float* __restrict__ hV,
                                             const float* __restrict__ W1,
                                             const float* __restrict__ b1,
                                             int ntok) {
    for (int i = blockIdx.x * 128 + threadIdx.x; i < ntok * H; i += gridDim.x * 128)
        g_dh[i] = 0.f;
    extern __shared__ float smf[];
    float* w1a = smf;
    float* w1c = smf + H * H;
    float* rows = smf + 2 * H * H;
    int tid = threadIdx.x;
    for (int i = tid; i < H * H; i += 128) {
        w1a[i] = W1[i];
        w1c[i] = W1[2 * H * H + i];
    }
    int t0 = blockIdx.x * 32;
    for (int i = tid; i < 32 * H; i += 128) rows[i] = hV[(size_t)t0 * H + i];
    __syncthreads();
    float bn = b1[tid];
    for (int rr = 0; rr < 32; rr++) {
        float a1 = bn, a3 = 0.f;
        const float4* rv = reinterpret_cast<const float4*>(rows + rr * H);
        #pragma unroll 8
        for (int k4 = 0; k4 < 32; k4++) {
            float4 v = rv[k4];
            int k = k4 * 4;
            a1 = fmaf(v.x, w1a[(k+0)*H+tid], a1); a1 = fmaf(v.y, w1a[(k+1)*H+tid], a1);
            a1 = fmaf(v.z, w1a[(k+2)*H+tid], a1); a1 = fmaf(v.w, w1a[(k+3)*H+tid], a1);
            a3 = fmaf(v.x, w1c[(k+0)*H+tid], a3); a3 = fmaf(v.y, w1c[(k+1)*H+tid], a3);
            a3 = fmaf(v.z, w1c[(k+2)*H+tid], a3); a3 = fmaf(v.w, w1c[(k+3)*H+tid], a3);
        }
        g_P1[(size_t)(t0+rr)*H+tid] = a1;
        g_P3[(size_t)(t0+rr)*H+tid] = a3;
    }
}

// 256 threads: 8 warps for latency hiding (was 4)
__global__ void __launch_bounds__(256, 1) k_ffn(
    const float* __restrict__ maskV,
    const float* __restrict__ W_in,  const float* __restrict__ b_in,
    const float* __restrict__ W_out, const float* __restrict__ b_out,
    const float* __restrict__ g2,    const float* __restrict__ be2,
    const float* __restrict__ W11,   const float* __restrict__ b11,
    float* __restrict__ outV) {
    extern __shared__ float smf[];
    float* sX   = smf;               // 32*H
    float* sHid = smf + 32 * H;      // 32*512
    float* sMk  = sHid + 32 * 512;   // 32
    int tid = threadIdx.x;
    int t0 = blockIdx.x * 32;
    int half = tid >> 7, col = tid & 127;
    for (int i = tid; i < 32 * H; i += 256) sX[i] = g_HV1[(size_t)t0 * H + i];
    if (tid < 32) sMk[tid] = maskV[t0 + tid];
    __syncthreads();

    // hidden layer: 512 cols, 2 per thread
    for (int cc = 0; cc < 2; cc++) {
        int c = cc * 256 + tid;
        float acc[32];
        float bi = b_in[c];
        #pragma unroll
        for (int rr = 0; rr < 32; rr++) acc[rr] = bi;
        gemm_acc<32, 32>(acc, sX, W_in, c, 512);
        #pragma unroll
        for (int rr = 0; rr < 32; rr++) sHid[rr * 512 + c] = gelu_f(acc[rr]);
    }
    __syncthreads();

    // output layer + residual: each thread 16 rows of one column
    {
        float acc[16];
        float bo = b_out[col];
        #pragma unroll
        for (int rr = 0; rr < 16; rr++) acc[rr] = bo;
        gemm_acc<16, 128>(acc, sHid + half * 16 * 512, W_out, col, H);
        #pragma unroll
        for (int rr = 0; rr < 16; rr++)
            acc[rr] += sX[(half * 16 + rr) * H + col];
        __syncthreads();
        #pragma unroll
        for (int rr = 0; rr < 16; rr++)
            sHid[(half * 16 + rr) * H + col] = acc[rr];
    }
    __syncthreads();

    // per-row LN + mask (8 warps, 4 rows each)
    {
        int warp = tid >> 5, lane = tid & 31;
        for (int rr = warp; rr < 32; rr += 8) {
            const float* row = sHid + rr * H;
            float v[4] = { row[lane], row[lane+32], row[lane+64], row[lane+96] };
            float s = v[0]+v[1]+v[2]+v[3];
            float s2 = v[0]*v[0]+v[1]*v[1]+v[2]*v[2]+v[3]*v[3];
            #pragma unroll
            for (int o = 16; o; o >>= 1) {
                s  += __shfl_xor_sync(0xffffffffu, s,  o);
                s2 += __shfl_xor_sync(0xffffffffu, s2, o);
            }
            float m = s * (1.f/H);
            float rs = rsqrtf(s2 * (1.f/H) - m*m + 1e-5f);
            float mk = sMk[rr];
            #pragma unroll
            for (int j = 0; j < 4; j++) {
                int n = lane + 32*j;
                float y = mk * (g2[n]*(v[j]-m)*rs + be2[n]);
                outV[(size_t)(t0+rr)*H + n] = y;
                sX[rr*H + n] = y;
            }
        }
    }
    __syncthreads();

    // P11 / P13 precompute: each thread 16 rows of one column
    {
        float acc2[16];
        float bb = b11[col];
        #pragma unroll
        for (int rr = 0; rr < 16; rr++) acc2[rr] = bb;
        gemm_acc<16, 32>(acc2, sX + half * 16 * H, W11, col, H);
        #pragma unroll
        for (int rr = 0; rr < 16; rr++)
            g_P11[(size_t)(t0 + half * 16 + rr) * H + col] = acc2[rr];
        #pragma unroll
        for (int rr = 0; rr < 16; rr++) acc2[rr] = 0.f;
        gemm_acc<16, 32>(acc2, sX + half * 16 * H, W11 + 2 * H * H, col, H);
        #pragma unroll
        for (int rr = 0; rr < 16; rr++)
            g_P13[(size_t)(t0 + half * 16 + rr) * H + col] = acc2[rr];
    }
}

// ---------------------------------------------------------------------------
extern "C" void kernel_launch(void* const* d_in, const int* in_sizes, int n_in,
                              void* d_out, int out_size) {
    const float* hV    = (const float*)d_in[0];
    const float* hE    = (const float*)d_in[1];
    const int*   Eidx  = (const int*)  d_in[2];
    const float* maskV = (const float*)d_in[3];
    const float* matt  = (const float*)d_in[4];
    const float* W1    = (const float*)d_in[5];
    const float* b1    = (const float*)d_in[6];
    const float* W2    = (const float*)d_in[7];
    const float* b2    = (const float*)d_in[8];
    const float* W3    = (const float*)d_in[9];
    const float* b3    = (const float*)d_in[10];
    const float* W11   = (const float*)d_in[11];
    const float* b11   = (const float*)d_in[12];
    const float* W12   = (const float*)d_in[13];
    const float* b12   = (const float*)d_in[14];
    const float* W13   = (const float*)d_in[15];
    const float* b13   = (const float*)d_in[16];
    const float* g1    = (const float*)d_in[17];
    const float* be1   = (const float*)d_in[18];
    const float* g2    = (const float*)d_in[19];
    const float* be2   = (const float*)d_in[20];
    const float* g3    = (const float*)d_in[21];
    const float* be3   = (const float*)d_in[22];
    const float* W_in  = (const float*)d_in[23];
    const float* b_in  = (const float*)d_in[24];
    const float* W_out = (const float*)d_in[25];
    const float* b_out = (const float*)d_in[26];

    int ntok = in_sizes[3];

    size_t smemP = (size_t)(2 * H * H + 32 * H) * sizeof(float);
    size_t smemB = (size_t)(32 * H + 32 * 512 + 64) * sizeof(float);

    cudaFuncSetAttribute(k_pre,    cudaFuncAttributeMaxDynamicSharedMemorySize, (int)smemP);
    cudaFuncSetAttribute(k_ffn,    cudaFuncAttributeMaxDynamicSharedMemorySize, (int)smemB);
    cudaFuncSetAttribute(k_mlp<0>, cudaFuncAttributeMaxDynamicSharedMemorySize, SMEM_MLP);
    cudaFuncSetAttribute(k_mlp<1>, cudaFuncAttributeMaxDynamicSharedMemorySize, SMEM_MLP);

    float* outV = (float*)d_out;
    float* outE = outV + (size_t)ntok * H;
    int ntile = ntok * KNB / 128;

    k_wprep<<< 6 * 16384 / 256, 256 >>>(W1 + H * H, W2, W3, W11 + H * H, W12, W13);
    k_pre  <<< ntok / 32, 128, smemP >>>(hV, W1, b1, ntok);
    k_mlp<0><<< ntile, 256, SMEM_MLP >>>(hE, Eidx, b2, b3, g1, be1, matt, outE);
    k_ln1  <<< ntok, 128 >>>(hV, g1, be1);
    k_ffn  <<< ntok / 32, 256, smemB >>>(maskV, W_in, b_in, W_out, b_out, g2, be2, W11, b11, outV);
    k_mlp<1><<< ntile, 256, SMEM_MLP >>>(hE, Eidx, b12, b13, g3, be3, matt, outE);
}

// round 7
// speedup vs baseline: 2.1772x; 1.0864x over previous
#include <cuda_runtime.h>
#include <cuda_bf16.h>
#include <math.h>
#include <cstdint>

#define H    128
#define KNB  48
#define LSEQ 2048
#define NTOK_MAX 4096

// ---------------- device scratch ----------------
__device__ float g_P1 [NTOK_MAX * H];
__device__ float g_P3 [NTOK_MAX * H];
__device__ float g_HV1[NTOK_MAX * H];
__device__ float g_P11[NTOK_MAX * H];
__device__ float g_P13[NTOK_MAX * H];
__device__ float g_dh [NTOK_MAX * H];
// 6 weight mats, transposed [n][k], hi then lo (each 16384 bf16)
__device__ __nv_bfloat16 g_W[6 * 32768];

__device__ __forceinline__ float gelu_f(float x) {
    return 0.5f * x * (1.0f + erff(x * 0.70710678118654752f));
}

__device__ __forceinline__ void split2(float a, float b, uint32_t& hi, uint32_t& lo) {
    __nv_bfloat162 h = __floats2bfloat162_rn(a, b);
    __nv_bfloat162 l = __floats2bfloat162_rn(a - __bfloat162float(h.x),
                                             b - __bfloat162float(h.y));
    hi = *reinterpret_cast<uint32_t*>(&h);
    lo = *reinterpret_cast<uint32_t*>(&l);
}

__device__ __forceinline__ uint32_t smem_u32(const void* p) {
    uint32_t a;
    asm("{ .reg .u64 t; cvta.to.shared.u64 t, %1; cvt.u32.u64 %0, t; }" : "=r"(a) : "l"(p));
    return a;
}

__device__ __forceinline__ void mma16816(float* c, const uint32_t* a,
                                         uint32_t b0, uint32_t b1) {
    asm volatile(
        "mma.sync.aligned.m16n8k16.row.col.f32.bf16.bf16.f32 "
        "{%0,%1,%2,%3}, {%4,%5,%6,%7}, {%8,%9}, {%0,%1,%2,%3};"
        : "+f"(c[0]), "+f"(c[1]), "+f"(c[2]), "+f"(c[3])
        : "r"(a[0]), "r"(a[1]), "r"(a[2]), "r"(a[3]), "r"(b0), "r"(b1));
}

#define LDSM4(r0, r1, r2, r3, addr) \
    asm volatile("ldmatrix.sync.aligned.m8n8.x4.shared.b16 {%0,%1,%2,%3}, [%4];" \
                 : "=r"(r0), "=r"(r1), "=r"(r2), "=r"(r3) : "r"(addr))

#define CP_COMMIT() asm volatile("cp.async.commit_group;" ::: "memory")
#define CP_WAIT0()  asm volatile("cp.async.wait_group 0;" ::: "memory")

// ---------------- smem layout (bytes) ----------------
#define LDA    136
#define STG_LD 130
#define SLAB  34816          // 128*136*2
#define SM_W0   0            // weight buffer 0: hi slab + lo slab (69632)
#define SM_W1   69632        // weight buffer 1
#define SM_A    139264       // activations: hi slab + lo slab (69632)
#define SM_NBR  208896       // 128 int
#define SM_MASK 209408       // 128 f
#define SM_B2   209920
#define SM_B3   210432
#define SM_G    210944
#define SM_BE   211456
#define SM_PAR  211968       // 1024 f = 4096
#define SMEM_MLP 216064

// ---------------- weight prep: transpose + bf16 hi/lo split ----------------
__global__ void k_wprep(const float* W1b, const float* W2, const float* W3,
                        const float* W11b, const float* W12, const float* W13) {
    int id = blockIdx.x * 256 + threadIdx.x;    // 6*16384
    int m = id >> 14, e = id & 16383;
    int n = e >> 7, k = e & 127;
    const float* srcs[6] = {W1b, W2, W3, W11b, W12, W13};
    float v = srcs[m][k * H + n];
    __nv_bfloat16 h = __float2bfloat16(v);
    g_W[m * 32768 + e]         = h;
    g_W[m * 32768 + 16384 + e] = __float2bfloat16(v - __bfloat162float(h));
}

// async weight load (512 threads): 4096 x 16B
__device__ __forceinline__ void load_w_async(uint32_t smDst, int tid, int mat) {
    const char* src = (const char*)(g_W + (size_t)mat * 32768);
    #pragma unroll
    for (int it = 0; it < 8; it++) {
        int id = tid + it * 512;
        int hl = id >> 11, j = id & 2047;
        int n = j >> 4, kc = (j & 15) << 3;
        uint32_t dst = smDst + hl * SLAB + (uint32_t)((n * LDA + kc) * 2);
        asm volatile("cp.async.cg.shared.global [%0], [%1], 16;"
                     :: "r"(dst), "l"(src + (size_t)id * 16));
    }
}

// 3-pass hi/lo GEMM via ldmatrix: acc[4][8] += A(128x128) x W^T (warp: 32x32)
__device__ __forceinline__ void do_gemm(uint32_t wBase, uint32_t aBase, float acc[4][8],
                                        int rowbase, int colq, int lane) {
    int arow = rowbase + (lane & 15);
    int acol = (lane >> 4) << 3;
    uint32_t aOff = aBase + (uint32_t)((arow * LDA + acol) * 2);
    int nrow = colq * 32 + (lane & 7) + ((lane >> 4) << 3);
    int bcol = ((lane >> 3) & 1) << 3;
    uint32_t bOff = wBase + (uint32_t)((nrow * LDA + bcol) * 2);
    #pragma unroll 1
    for (int pass = 0; pass < 3; pass++) {
        uint32_t aB = aOff + ((pass == 2) ? SLAB : 0);
        uint32_t bB = bOff + ((pass == 1) ? SLAB : 0);
        #pragma unroll 1
        for (int ks = 0; ks < 8; ks++) {
            uint32_t a0[4], a1[4];
            LDSM4(a0[0], a0[1], a0[2], a0[3], aB + ks * 32);
            LDSM4(a1[0], a1[1], a1[2], a1[3], aB + 16 * LDA * 2 + ks * 32);
            #pragma unroll
            for (int ntp = 0; ntp < 2; ntp++) {
                uint32_t b0, b1, b2, b3;
                LDSM4(b0, b1, b2, b3, bB + ntp * 16 * LDA * 2 + ks * 32);
                mma16816(&acc[2 * ntp][0],     a0, b0, b1);
                mma16816(&acc[2 * ntp][4],     a1, b0, b1);
                mma16816(&acc[2 * ntp + 1][0], a0, b2, b3);
                mma16816(&acc[2 * ntp + 1][4], a1, b2, b3);
            }
        }
    }
}

// GELU(acc) -> A slabs (bf16 hi/lo)
__device__ __forceinline__ void epi_act(char* sm, float acc[4][8],
                                        int rowbase, int colq, int gid, int tig) {
    #pragma unroll
    for (int nt = 0; nt < 4; nt++) {
        int col = colq * 32 + nt * 8 + 2 * tig;
        #pragma unroll
        for (int q = 0; q < 4; q++) {
            int row = rowbase + q * 8 + gid;
            float v0 = gelu_f(acc[nt][q * 2]);
            float v1 = gelu_f(acc[nt][q * 2 + 1]);
            uint32_t hi, lo;
            split2(v0, v1, hi, lo);
            int boff = (row * LDA + col) * 2;
            *(uint32_t*)(sm + SM_A + boff)        = hi;
            *(uint32_t*)(sm + SM_A + SLAB + boff) = lo;
        }
    }
}

// ---------------- fused 3-layer MLP over one 128-row tile (512 thr) ----------
// MODE 0: node messages -> masked per-token sums into g_dh (atomic)
// MODE 1: edge update -> +hE residual, row LN, write outE
template <int MODE>
__global__ void __launch_bounds__(512, 1) k_mlp(
    const float* __restrict__ hE, const int* __restrict__ Eidx,
    const float* __restrict__ bias2, const float* __restrict__ bias3,
    const float* __restrict__ lng, const float* __restrict__ lnb,
    const float* __restrict__ mattend, float* __restrict__ outE) {
    extern __shared__ char sm[];
    int*   snbr  = (int*)(sm + SM_NBR);
    float* smask = (float*)(sm + SM_MASK);
    float* sb2   = (float*)(sm + SM_B2);
    float* sb3   = (float*)(sm + SM_B3);
    float* sg    = (float*)(sm + SM_G);
    float* sbe   = (float*)(sm + SM_BE);
    float* spar  = (float*)(sm + SM_PAR);

    int tid = threadIdx.x, wid = tid >> 5, lane = tid & 31;
    int gid = lane >> 2, tig = lane & 3;
    int rowbase = (wid & 3) * 32;       // 4 row groups
    int colq = wid >> 2;                // 4 col quarters (32 cols each)
    int grow0 = blockIdx.x * 128;
    uint32_t smb = smem_u32(sm);

    // start weight prefetch for layer 1 immediately
    load_w_async(smb + SM_W0, tid, MODE * 3 + 0);
    CP_COMMIT();

    if (tid < 128) {
        int gr = grow0 + tid;
        int t = gr / KNB;
        snbr[tid] = (t / LSEQ) * LSEQ + Eidx[gr];
        smask[tid] = (MODE == 0) ? mattend[gr] : 0.f;
        sb2[tid] = bias2[tid]; sb3[tid] = bias3[tid];
        sg[tid] = lng[tid];    sbe[tid] = lnb[tid];
    }

    // A <- split(hE tile)
    const float4* hE4 = reinterpret_cast<const float4*>(hE + (size_t)grow0 * H);
    #pragma unroll
    for (int it = 0; it < 8; it++) {
        int id = tid + it * 512;
        int rr = id >> 5, c4 = id & 31;
        float4 v = hE4[rr * 32 + c4];
        uint32_t h01, l01, h23, l23;
        split2(v.x, v.y, h01, l01);
        split2(v.z, v.w, h23, l23);
        int boff = (rr * LDA + c4 * 4) * 2;
        *(uint2*)(sm + SM_A + boff)        = make_uint2(h01, h23);
        *(uint2*)(sm + SM_A + SLAB + boff) = make_uint2(l01, l23);
    }
    CP_WAIT0();
    __syncthreads();

    float acc[4][8];

    // ---- layer 1: acc init = P_center + P_nbr (direct from global) ----
    {
        const float* Padd = (MODE == 0) ? g_P1 : g_P11;
        const float* Pnbr = (MODE == 0) ? g_P3 : g_P13;
        int tokv[4], nbv[4];
        #pragma unroll
        for (int q = 0; q < 4; q++) {
            int row = rowbase + q * 8 + gid;
            tokv[q] = (grow0 + row) / KNB;
            nbv[q] = snbr[row];
        }
        #pragma unroll
        for (int nt = 0; nt < 4; nt++) {
            int col = colq * 32 + nt * 8 + 2 * tig;
            #pragma unroll
            for (int q = 0; q < 4; q++) {
                float2 a = *(const float2*)(Padd + (size_t)tokv[q] * H + col);
                float2 b = *(const float2*)(Pnbr + (size_t)nbv[q] * H + col);
                acc[nt][q * 2] = a.x + b.x; acc[nt][q * 2 + 1] = a.y + b.y;
            }
        }
    }
    load_w_async(smb + SM_W1, tid, MODE * 3 + 1);   // prefetch layer 2
    CP_COMMIT();
    do_gemm(smb + SM_W0, smb + SM_A, acc, rowbase, colq, lane);
    CP_WAIT0();
    __syncthreads();
    epi_act(sm, acc, rowbase, colq, gid, tig);
    __syncthreads();

    // ---- layer 2 ----
    #pragma unroll
    for (int nt = 0; nt < 4; nt++) {
        int col = colq * 32 + nt * 8 + 2 * tig;
        float b0 = sb2[col], b1 = sb2[col + 1];
        #pragma unroll
        for (int q = 0; q < 4; q++) { acc[nt][q * 2] = b0; acc[nt][q * 2 + 1] = b1; }
    }
    load_w_async(smb + SM_W0, tid, MODE * 3 + 2);   // prefetch layer 3 into buf0
    CP_COMMIT();
    do_gemm(smb + SM_W1, smb + SM_A, acc, rowbase, colq, lane);
    CP_WAIT0();
    __syncthreads();
    epi_act(sm, acc, rowbase, colq, gid, tig);
    __syncthreads();

    // ---- layer 3 ----
    #pragma unroll
    for (int nt = 0; nt < 4; nt++) {
        int col = colq * 32 + nt * 8 + 2 * tig;
        float b0 = sb3[col], b1 = sb3[col + 1];
        #pragma unroll
        for (int q = 0; q < 4; q++) { acc[nt][q * 2] = b0; acc[nt][q * 2 + 1] = b1; }
    }
    do_gemm(smb + SM_W0, smb + SM_A, acc, rowbase, colq, lane);

    if (MODE == 0) {
        // masked values -> A region (now dead), then per-token column sums
        __syncthreads();
        float* fA = (float*)(sm + SM_A);
        #pragma unroll
        for (int nt = 0; nt < 4; nt++) {
            int col = colq * 32 + nt * 8 + 2 * tig;
            #pragma unroll
            for (int q = 0; q < 4; q++) {
                int row = rowbase + q * 8 + gid;
                float mk = smask[row];
                *(float2*)(fA + row * STG_LD + col) =
                    make_float2(mk * acc[nt][q * 2], mk * acc[nt][q * 2 + 1]);
            }
        }
        __syncthreads();
        int c = tid & 127, qtr = tid >> 7;
        int t0 = grow0 / KNB;
        for (int tok = t0 + qtr; KNB * tok < grow0 + 128; tok += 4) {
            int r0 = KNB * tok - grow0, r1 = r0 + KNB;
            if (r0 < 0) r0 = 0;
            if (r1 > 128) r1 = 128;
            float s = 0.f;
            for (int rr = r0; rr < r1; rr++) s += fA[rr * STG_LD + c];
            atomicAdd(&g_dh[(size_t)tok * H + c], s);
        }
    } else {
        // residual + per-row LN -> outE
        float sA[4], sB[4];
        #pragma unroll
        for (int q = 0; q < 4; q++) { sA[q] = 0.f; sB[q] = 0.f; }
        #pragma unroll
        for (int nt = 0; nt < 4; nt++) {
            int col = colq * 32 + nt * 8 + 2 * tig;
            #pragma unroll
            for (int q = 0; q < 4; q++) {
                int row = rowbase + q * 8 + gid;
                float2 res = *(const float2*)(hE + (size_t)(grow0 + row) * H + col);
                float x0 = acc[nt][q * 2]     + res.x;
                float x1 = acc[nt][q * 2 + 1] + res.y;
                acc[nt][q * 2] = x0; acc[nt][q * 2 + 1] = x1;
                sA[q] += x0 + x1;
                sB[q] += x0 * x0 + x1 * x1;
            }
        }
        #pragma unroll
        for (int q = 0; q < 4; q++) {
            sA[q] += __shfl_xor_sync(0xffffffffu, sA[q], 1);
            sA[q] += __shfl_xor_sync(0xffffffffu, sA[q], 2);
            sB[q] += __shfl_xor_sync(0xffffffffu, sB[q], 1);
            sB[q] += __shfl_xor_sync(0xffffffffu, sB[q], 2);
        }
        if (tig == 0) {
            #pragma unroll
            for (int q = 0; q < 4; q++) {
                int row = rowbase + q * 8 + gid;
                spar[colq * 128 + row]       = sA[q];
                spar[512 + colq * 128 + row] = sB[q];
            }
        }
        __syncthreads();
        float mV = 0.f, rV = 0.f;
        if (tid < 128) {
            float ss  = spar[tid] + spar[128 + tid] + spar[256 + tid] + spar[384 + tid];
            float ss2 = spar[512 + tid] + spar[640 + tid] + spar[768 + tid] + spar[896 + tid];
            mV = ss * (1.f / H);
            rV = rsqrtf(ss2 * (1.f / H) - mV * mV + 1e-5f);
        }
        __syncthreads();
        if (tid < 128) { spar[tid] = mV; spar[128 + tid] = rV; }
        __syncthreads();
        #pragma unroll
        for (int nt = 0; nt < 4; nt++) {
            int col = colq * 32 + nt * 8 + 2 * tig;
            float g0 = sg[col], g1 = sg[col + 1];
            float e0 = sbe[col], e1 = sbe[col + 1];
            #pragma unroll
            for (int q = 0; q < 4; q++) {
                int row = rowbase + q * 8 + gid;
                float m = spar[row], rs = spar[128 + row];
                float2 y;
                y.x = g0 * (acc[nt][q * 2]     - m) * rs + e0;
                y.y = g1 * (acc[nt][q * 2 + 1] - m) * rs + e1;
                *(float2*)(outE + (size_t)(grow0 + row) * H + col) = y;
            }
        }
    }
}

// ---------------- node LN after dh accumulation ----------------
__global__ void __launch_bounds__(128) k_ln1(const float* __restrict__ hV,
                                             const float* __restrict__ g1,
                                             const float* __restrict__ be1) {
    __shared__ float red[8];
    int tid = threadIdx.x, t = blockIdx.x;
    float x = hV[(size_t)t * H + tid] + g_dh[(size_t)t * H + tid] * (1.f / 30.f);
    float s = x, s2 = x * x;
    #pragma unroll
    for (int o = 16; o; o >>= 1) {
        s  += __shfl_xor_sync(0xffffffffu, s,  o);
        s2 += __shfl_xor_sync(0xffffffffu, s2, o);
    }
    if ((tid & 31) == 0) { red[tid >> 5] = s; red[4 + (tid >> 5)] = s2; }
    __syncthreads();
    s  = red[0] + red[1] + red[2] + red[3];
    s2 = red[4] + red[5] + red[6] + red[7];
    float m = s * (1.f / H);
    float rs = rsqrtf(s2 * (1.f / H) - m * m + 1e-5f);
    g_HV1[(size_t)t * H + tid] = g1[tid] * (x - m) * rs + be1[tid];
}

// ---------------- fp32 helpers for pre / ffn ----------------
template<int ROWS, int K4>
__device__ __forceinline__ void gemm_acc(float* acc, const float* A,
                                         const float* __restrict__ W,
                                         int n, int ldw) {
    const float4* A4 = reinterpret_cast<const float4*>(A);
    #pragma unroll 1
    for (int k4 = 0; k4 < K4; k4++) {
        const float* wp = W + (k4 * 4) * ldw + n;
        float w0 = wp[0], w1 = wp[ldw], w2 = wp[2 * ldw], w3 = wp[3 * ldw];
        #pragma unroll
        for (int rr = 0; rr < ROWS; rr++) {
            float4 a = A4[rr * K4 + k4];
            acc[rr] = fmaf(a.x, w0, acc[rr]);
            acc[rr] = fmaf(a.y, w1, acc[rr]);
            acc[rr] = fmaf(a.z, w2, acc[rr]);
            acc[rr] = fmaf(a.w, w3, acc[rr]);
        }
    }
}

__global__ void __launch_bounds__(128) k_pre(const float* __restrict__ hV,
                                             const float* __restrict__ W1,
                                             const float* __restrict__ b1,
                                             int ntok) {
    for (int i = blockIdx.x * 128 + threadIdx.x; i < ntok * H; i += gridDim.x * 128)
        g_dh[i] = 0.f;
    extern __shared__ float smf[];
    float* w1a = smf;
    float* w1c = smf + H * H;
    float* rows = smf + 2 * H * H;
    int tid = threadIdx.x;
    for (int i = tid; i < H * H; i += 128) {
        w1a[i] = W1[i];
        w1c[i] = W1[2 * H * H + i];
    }
    int t0 = blockIdx.x * 32;
    for (int i = tid; i < 32 * H; i += 128) rows[i] = hV[(size_t)t0 * H + i];
    __syncthreads();
    float bn = b1[tid];
    for (int rr = 0; rr < 32; rr++) {
        float a1 = bn, a3 = 0.f;
        const float4* rv = reinterpret_cast<const float4*>(rows + rr * H);
        #pragma unroll 8
        for (int k4 = 0; k4 < 32; k4++) {
            float4 v = rv[k4];
            int k = k4 * 4;
            a1 = fmaf(v.x, w1a[(k+0)*H+tid], a1); a1 = fmaf(v.y, w1a[(k+1)*H+tid], a1);
            a1 = fmaf(v.z, w1a[(k+2)*H+tid], a1); a1 = fmaf(v.w, w1a[(k+3)*H+tid], a1);
            a3 = fmaf(v.x, w1c[(k+0)*H+tid], a3); a3 = fmaf(v.y, w1c[(k+1)*H+tid], a3);
            a3 = fmaf(v.z, w1c[(k+2)*H+tid], a3); a3 = fmaf(v.w, w1c[(k+3)*H+tid], a3);
        }
        g_P1[(size_t)(t0+rr)*H+tid] = a1;
        g_P3[(size_t)(t0+rr)*H+tid] = a3;
    }
}

__global__ void __launch_bounds__(256, 1) k_ffn(
    const float* __restrict__ maskV,
    const float* __restrict__ W_in,  const float* __restrict__ b_in,
    const float* __restrict__ W_out, const float* __restrict__ b_out,
    const float* __restrict__ g2,    const float* __restrict__ be2,
    const float* __restrict__ W11,   const float* __restrict__ b11,
    float* __restrict__ outV) {
    extern __shared__ float smf[];
    float* sX   = smf;               // 32*H
    float* sHid = smf + 32 * H;      // 32*512
    float* sMk  = sHid + 32 * 512;   // 32
    int tid = threadIdx.x;
    int t0 = blockIdx.x * 32;
    int half = tid >> 7, col = tid & 127;
    for (int i = tid; i < 32 * H; i += 256) sX[i] = g_HV1[(size_t)t0 * H + i];
    if (tid < 32) sMk[tid] = maskV[t0 + tid];
    __syncthreads();

    for (int cc = 0; cc < 2; cc++) {
        int c = cc * 256 + tid;
        float acc[32];
        float bi = b_in[c];
        #pragma unroll
        for (int rr = 0; rr < 32; rr++) acc[rr] = bi;
        gemm_acc<32, 32>(acc, sX, W_in, c, 512);
        #pragma unroll
        for (int rr = 0; rr < 32; rr++) sHid[rr * 512 + c] = gelu_f(acc[rr]);
    }
    __syncthreads();

    {
        float acc[16];
        float bo = b_out[col];
        #pragma unroll
        for (int rr = 0; rr < 16; rr++) acc[rr] = bo;
        gemm_acc<16, 128>(acc, sHid + half * 16 * 512, W_out, col, H);
        #pragma unroll
        for (int rr = 0; rr < 16; rr++)
            acc[rr] += sX[(half * 16 + rr) * H + col];
        __syncthreads();
        #pragma unroll
        for (int rr = 0; rr < 16; rr++)
            sHid[(half * 16 + rr) * H + col] = acc[rr];
    }
    __syncthreads();

    {
        int warp = tid >> 5, lane = tid & 31;
        for (int rr = warp; rr < 32; rr += 8) {
            const float* row = sHid + rr * H;
            float v[4] = { row[lane], row[lane+32], row[lane+64], row[lane+96] };
            float s = v[0]+v[1]+v[2]+v[3];
            float s2 = v[0]*v[0]+v[1]*v[1]+v[2]*v[2]+v[3]*v[3];
            #pragma unroll
            for (int o = 16; o; o >>= 1) {
                s  += __shfl_xor_sync(0xffffffffu, s,  o);
                s2 += __shfl_xor_sync(0xffffffffu, s2, o);
            }
            float m = s * (1.f/H);
            float rs = rsqrtf(s2 * (1.f/H) - m*m + 1e-5f);
            float mk = sMk[rr];
            #pragma unroll
            for (int j = 0; j < 4; j++) {
                int n = lane + 32*j;
                float y = mk * (g2[n]*(v[j]-m)*rs + be2[n]);
                outV[(size_t)(t0+rr)*H + n] = y;
                sX[rr*H + n] = y;
            }
        }
    }
    __syncthreads();

    {
        float acc2[16];
        float bb = b11[col];
        #pragma unroll
        for (int rr = 0; rr < 16; rr++) acc2[rr] = bb;
        gemm_acc<16, 32>(acc2, sX + half * 16 * H, W11, col, H);
        #pragma unroll
        for (int rr = 0; rr < 16; rr++)
            g_P11[(size_t)(t0 + half * 16 + rr) * H + col] = acc2[rr];
        #pragma unroll
        for (int rr = 0; rr < 16; rr++) acc2[rr] = 0.f;
        gemm_acc<16, 32>(acc2, sX + half * 16 * H, W11 + 2 * H * H, col, H);
        #pragma unroll
        for (int rr = 0; rr < 16; rr++)
            g_P13[(size_t)(t0 + half * 16 + rr) * H + col] = acc2[rr];
    }
}

// ---------------------------------------------------------------------------
extern "C" void kernel_launch(void* const* d_in, const int* in_sizes, int n_in,
                              void* d_out, int out_size) {
    const float* hV    = (const float*)d_in[0];
    const float* hE    = (const float*)d_in[1];
    const int*   Eidx  = (const int*)  d_in[2];
    const float* maskV = (const float*)d_in[3];
    const float* matt  = (const float*)d_in[4];
    const float* W1    = (const float*)d_in[5];
    const float* b1    = (const float*)d_in[6];
    const float* W2    = (const float*)d_in[7];
    const float* b2    = (const float*)d_in[8];
    const float* W3    = (const float*)d_in[9];
    const float* b3    = (const float*)d_in[10];
    const float* W11   = (const float*)d_in[11];
    const float* b11   = (const float*)d_in[12];
    const float* W12   = (const float*)d_in[13];
    const float* b12   = (const float*)d_in[14];
    const float* W13   = (const float*)d_in[15];
    const float* b13   = (const float*)d_in[16];
    const float* g1    = (const float*)d_in[17];
    const float* be1   = (const float*)d_in[18];
    const float* g2    = (const float*)d_in[19];
    const float* be2   = (const float*)d_in[20];
    const float* g3    = (const float*)d_in[21];
    const float* be3   = (const float*)d_in[22];
    const float* W_in  = (const float*)d_in[23];
    const float* b_in  = (const float*)d_in[24];
    const float* W_out = (const float*)d_in[25];
    const float* b_out = (const float*)d_in[26];

    int ntok = in_sizes[3];

    size_t smemP = (size_t)(2 * H * H + 32 * H) * sizeof(float);
    size_t smemB = (size_t)(32 * H + 32 * 512 + 64) * sizeof(float);

    cudaFuncSetAttribute(k_pre,    cudaFuncAttributeMaxDynamicSharedMemorySize, (int)smemP);
    cudaFuncSetAttribute(k_ffn,    cudaFuncAttributeMaxDynamicSharedMemorySize, (int)smemB);
    cudaFuncSetAttribute(k_mlp<0>, cudaFuncAttributeMaxDynamicSharedMemorySize, SMEM_MLP);
    cudaFuncSetAttribute(k_mlp<1>, cudaFuncAttributeMaxDynamicSharedMemorySize, SMEM_MLP);

    float* outV = (float*)d_out;
    float* outE = outV + (size_t)ntok * H;
    int ntile = ntok * KNB / 128;

    k_wprep<<< 6 * 16384 / 256, 256 >>>(W1 + H * H, W2, W3, W11 + H * H, W12, W13);
    k_pre  <<< ntok / 32, 128, smemP >>>(hV, W1, b1, ntok);
    k_mlp<0><<< ntile, 512, SMEM_MLP >>>(hE, Eidx, b2, b3, g1, be1, matt, outE);
    k_ln1  <<< ntok, 128 >>>(hV, g1, be1);
    k_ffn  <<< ntok / 32, 256, smemB >>>(maskV, W_in, b_in, W_out, b_out, g2, be2, W11, b11, outV);
    k_mlp<1><<< ntile, 512, SMEM_MLP >>>(hE, Eidx, b12, b13, g3, be3, matt, outE);
}

// round 8
// speedup vs baseline: 2.5273x; 1.1608x over previous
#include <cuda_runtime.h>
#include <cuda_fp16.h>
#include <math.h>
#include <cstdint>

#define H    128
#define KNB  48
#define LSEQ 2048
#define NTOK_MAX 4096

// ---------------- device scratch ----------------
__device__ float g_P1 [NTOK_MAX * H];
__device__ float g_P3 [NTOK_MAX * H];
__device__ float g_P11[NTOK_MAX * H];
__device__ float g_P13[NTOK_MAX * H];
__device__ float g_dh [NTOK_MAX * H];
// 6 weight mats, transposed [n][k], fp16 hi then fp16 lo (each 16384)
__device__ __half g_W[6 * 32768];

__device__ __forceinline__ float gelu_f(float x) {
    return 0.5f * x * (1.0f + erff(x * 0.70710678118654752f));
}

__device__ __forceinline__ uint32_t smem_u32(const void* p) {
    uint32_t a;
    asm("{ .reg .u64 t; cvta.to.shared.u64 t, %1; cvt.u32.u64 %0, t; }" : "=r"(a) : "l"(p));
    return a;
}

__device__ __forceinline__ void mma16816(float* c, const uint32_t* a,
                                         uint32_t b0, uint32_t b1) {
    asm volatile(
        "mma.sync.aligned.m16n8k16.row.col.f32.f16.f16.f32 "
        "{%0,%1,%2,%3}, {%4,%5,%6,%7}, {%8,%9}, {%0,%1,%2,%3};"
        : "+f"(c[0]), "+f"(c[1]), "+f"(c[2]), "+f"(c[3])
        : "r"(a[0]), "r"(a[1]), "r"(a[2]), "r"(a[3]), "r"(b0), "r"(b1));
}

#define LDSM4(r0, r1, r2, r3, addr) \
    asm volatile("ldmatrix.sync.aligned.m8n8.x4.shared.b16 {%0,%1,%2,%3}, [%4];" \
                 : "=r"(r0), "=r"(r1), "=r"(r2), "=r"(r3) : "r"(addr))

#define CP_COMMIT() asm volatile("cp.async.commit_group;" ::: "memory")
#define CP_WAIT0()  asm volatile("cp.async.wait_group 0;" ::: "memory")

// ---------------- smem layout (bytes) ----------------
#define LDA    136
#define STG_LD 130
#define SLAB  34816          // 128*136*2
#define SM_W0   0            // weight buf 0: hi slab + lo slab (69632)
#define SM_W1   69632        // weight buf 1 (also MODE0 staging late)
#define SM_A    139264       // activations: SINGLE fp16 slab (34816)
#define SM_NBR  174080       // 128 int
#define SM_MASK 174592       // 128 f
#define SM_B2   175104
#define SM_B3   175616
#define SM_G    176128
#define SM_BE   176640
#define SM_PAR  177152       // 1024 f = 4096
#define SMEM_MLP 181248

// ---------------- weight prep: transpose + fp16 hi/lo split ----------------
__global__ void k_wprep(const float* W1b, const float* W2, const float* W3,
                        const float* W11b, const float* W12, const float* W13) {
    int id = blockIdx.x * 256 + threadIdx.x;    // 6*16384
    int m = id >> 14, e = id & 16383;
    int n = e >> 7, k = e & 127;
    const float* srcs[6] = {W1b, W2, W3, W11b, W12, W13};
    float v = srcs[m][k * H + n];
    __half h = __float2half_rn(v);
    g_W[m * 32768 + e]         = h;
    g_W[m * 32768 + 16384 + e] = __float2half_rn(v - __half2float(h));
}

// async weight load (512 threads): 4096 x 16B
__device__ __forceinline__ void load_w_async(uint32_t smDst, int tid, int mat) {
    const char* src = (const char*)(g_W + (size_t)mat * 32768);
    #pragma unroll
    for (int it = 0; it < 8; it++) {
        int id = tid + it * 512;
        int hl = id >> 11, j = id & 2047;
        int n = j >> 4, kc = (j & 15) << 3;
        uint32_t dst = smDst + hl * SLAB + (uint32_t)((n * LDA + kc) * 2);
        asm volatile("cp.async.cg.shared.global [%0], [%1], 16;"
                     :: "r"(dst), "l"(src + (size_t)id * 16));
    }
}

// 2-pass GEMM (A fp16, W hi+lo): acc[4][8] += A(128x128) x W^T (warp: 32x32)
__device__ __forceinline__ void do_gemm(uint32_t wBase, uint32_t aBase, float acc[4][8],
                                        int rowbase, int colq, int lane) {
    int arow = rowbase + (lane & 15);
    int acol = (lane >> 4) << 3;
    uint32_t aOff = aBase + (uint32_t)((arow * LDA + acol) * 2);
    int nrow = colq * 32 + (lane & 7) + ((lane >> 4) << 3);
    int bcol = ((lane >> 3) & 1) << 3;
    uint32_t bOff = wBase + (uint32_t)((nrow * LDA + bcol) * 2);
    #pragma unroll 1
    for (int pass = 0; pass < 2; pass++) {
        uint32_t bB = bOff + ((pass == 1) ? SLAB : 0);
        #pragma unroll 1
        for (int ks = 0; ks < 8; ks++) {
            uint32_t a0[4], a1[4];
            LDSM4(a0[0], a0[1], a0[2], a0[3], aOff + ks * 32);
            LDSM4(a1[0], a1[1], a1[2], a1[3], aOff + 16 * LDA * 2 + ks * 32);
            #pragma unroll
            for (int ntp = 0; ntp < 2; ntp++) {
                uint32_t b0, b1, b2, b3;
                LDSM4(b0, b1, b2, b3, bB + ntp * 16 * LDA * 2 + ks * 32);
                mma16816(&acc[2 * ntp][0],     a0, b0, b1);
                mma16816(&acc[2 * ntp][4],     a1, b0, b1);
                mma16816(&acc[2 * ntp + 1][0], a0, b2, b3);
                mma16816(&acc[2 * ntp + 1][4], a1, b2, b3);
            }
        }
    }
}

// GELU(acc) -> A slab (fp16), for next layer's input
__device__ __forceinline__ void epi_act(char* sm, float acc[4][8],
                                        int rowbase, int colq, int gid, int tig) {
    #pragma unroll
    for (int nt = 0; nt < 4; nt++) {
        int col = colq * 32 + nt * 8 + 2 * tig;
        #pragma unroll
        for (int q = 0; q < 4; q++) {
            int row = rowbase + q * 8 + gid;
            __half2 h = __floats2half2_rn(gelu_f(acc[nt][q * 2]),
                                          gelu_f(acc[nt][q * 2 + 1]));
            *(uint32_t*)(sm + SM_A + (row * LDA + col) * 2) =
                *reinterpret_cast<uint32_t*>(&h);
        }
    }
}

// ---------------- fused 3-layer MLP over one 128-row tile (512 thr) ----------
// MODE 0: node messages -> masked per-token sums into g_dh (atomic)
// MODE 1: edge update -> +hE residual, row LN, write outE
template <int MODE>
__global__ void __launch_bounds__(512, 1) k_mlp(
    const float* __restrict__ hE, const int* __restrict__ Eidx,
    const float* __restrict__ bias2, const float* __restrict__ bias3,
    const float* __restrict__ lng, const float* __restrict__ lnb,
    const float* __restrict__ mattend, float* __restrict__ outE) {
    extern __shared__ char sm[];
    int*   snbr  = (int*)(sm + SM_NBR);
    float* smask = (float*)(sm + SM_MASK);
    float* sb2   = (float*)(sm + SM_B2);
    float* sb3   = (float*)(sm + SM_B3);
    float* sg    = (float*)(sm + SM_G);
    float* sbe   = (float*)(sm + SM_BE);
    float* spar  = (float*)(sm + SM_PAR);

    int tid = threadIdx.x, wid = tid >> 5, lane = tid & 31;
    int gid = lane >> 2, tig = lane & 3;
    int rowbase = (wid & 3) * 32;
    int colq = wid >> 2;
    int grow0 = blockIdx.x * 128;
    uint32_t smb = smem_u32(sm);

    load_w_async(smb + SM_W0, tid, MODE * 3 + 0);
    CP_COMMIT();

    if (tid < 128) {
        int gr = grow0 + tid;
        int t = gr / KNB;
        snbr[tid] = (t / LSEQ) * LSEQ + Eidx[gr];
        smask[tid] = (MODE == 0) ? mattend[gr] : 0.f;
        sb2[tid] = bias2[tid]; sb3[tid] = bias3[tid];
        sg[tid] = lng[tid];    sbe[tid] = lnb[tid];
    }

    // A <- fp16(hE tile)
    const float4* hE4 = reinterpret_cast<const float4*>(hE + (size_t)grow0 * H);
    #pragma unroll
    for (int it = 0; it < 8; it++) {
        int id = tid + it * 512;
        int rr = id >> 5, c4 = id & 31;
        float4 v = hE4[rr * 32 + c4];
        __half2 h01 = __floats2half2_rn(v.x, v.y);
        __half2 h23 = __floats2half2_rn(v.z, v.w);
        *(uint2*)(sm + SM_A + (rr * LDA + c4 * 4) * 2) =
            make_uint2(*reinterpret_cast<uint32_t*>(&h01),
                       *reinterpret_cast<uint32_t*>(&h23));
    }
    CP_WAIT0();
    __syncthreads();

    float acc[4][8];

    // ---- layer 1: acc init = P_center + P_nbr (exact fp32, from global) ----
    {
        const float* Padd = (MODE == 0) ? g_P1 : g_P11;
        const float* Pnbr = (MODE == 0) ? g_P3 : g_P13;
        int tokv[4], nbv[4];
        #pragma unroll
        for (int q = 0; q < 4; q++) {
            int row = rowbase + q * 8 + gid;
            tokv[q] = (grow0 + row) / KNB;
            nbv[q] = snbr[row];
        }
        #pragma unroll
        for (int nt = 0; nt < 4; nt++) {
            int col = colq * 32 + nt * 8 + 2 * tig;
            #pragma unroll
            for (int q = 0; q < 4; q++) {
                float2 a = *(const float2*)(Padd + (size_t)tokv[q] * H + col);
                float2 b = *(const float2*)(Pnbr + (size_t)nbv[q] * H + col);
                acc[nt][q * 2] = a.x + b.x; acc[nt][q * 2 + 1] = a.y + b.y;
            }
        }
    }
    load_w_async(smb + SM_W1, tid, MODE * 3 + 1);
    CP_COMMIT();
    do_gemm(smb + SM_W0, smb + SM_A, acc, rowbase, colq, lane);
    CP_WAIT0();
    __syncthreads();
    epi_act(sm, acc, rowbase, colq, gid, tig);
    __syncthreads();

    // ---- layer 2 ----
    #pragma unroll
    for (int nt = 0; nt < 4; nt++) {
        int col = colq * 32 + nt * 8 + 2 * tig;
        float b0 = sb2[col], b1 = sb2[col + 1];
        #pragma unroll
        for (int q = 0; q < 4; q++) { acc[nt][q * 2] = b0; acc[nt][q * 2 + 1] = b1; }
    }
    load_w_async(smb + SM_W0, tid, MODE * 3 + 2);
    CP_COMMIT();
    do_gemm(smb + SM_W1, smb + SM_A, acc, rowbase, colq, lane);
    CP_WAIT0();
    __syncthreads();
    epi_act(sm, acc, rowbase, colq, gid, tig);
    __syncthreads();

    // ---- layer 3 ----
    #pragma unroll
    for (int nt = 0; nt < 4; nt++) {
        int col = colq * 32 + nt * 8 + 2 * tig;
        float b0 = sb3[col], b1 = sb3[col + 1];
        #pragma unroll
        for (int q = 0; q < 4; q++) { acc[nt][q * 2] = b0; acc[nt][q * 2 + 1] = b1; }
    }
    do_gemm(smb + SM_W0, smb + SM_A, acc, rowbase, colq, lane);

    if (MODE == 0) {
        // masked values -> W1 region (dead), then per-token column sums
        __syncthreads();
        float* fA = (float*)(sm + SM_W1);
        #pragma unroll
        for (int nt = 0; nt < 4; nt++) {
            int col = colq * 32 + nt * 8 + 2 * tig;
            #pragma unroll
            for (int q = 0; q < 4; q++) {
                int row = rowbase + q * 8 + gid;
                float mk = smask[row];
                *(float2*)(fA + row * STG_LD + col) =
                    make_float2(mk * acc[nt][q * 2], mk * acc[nt][q * 2 + 1]);
            }
        }
        __syncthreads();
        int c = tid & 127, qtr = tid >> 7;
        int t0 = grow0 / KNB;
        for (int tok = t0 + qtr; KNB * tok < grow0 + 128; tok += 4) {
            int r0 = KNB * tok - grow0, r1 = r0 + KNB;
            if (r0 < 0) r0 = 0;
            if (r1 > 128) r1 = 128;
            float s = 0.f;
            for (int rr = r0; rr < r1; rr++) s += fA[rr * STG_LD + c];
            atomicAdd(&g_dh[(size_t)tok * H + c], s);
        }
    } else {
        // residual + per-row LN -> outE
        float sA[4], sB[4];
        #pragma unroll
        for (int q = 0; q < 4; q++) { sA[q] = 0.f; sB[q] = 0.f; }
        #pragma unroll
        for (int nt = 0; nt < 4; nt++) {
            int col = colq * 32 + nt * 8 + 2 * tig;
            #pragma unroll
            for (int q = 0; q < 4; q++) {
                int row = rowbase + q * 8 + gid;
                float2 res = *(const float2*)(hE + (size_t)(grow0 + row) * H + col);
                float x0 = acc[nt][q * 2]     + res.x;
                float x1 = acc[nt][q * 2 + 1] + res.y;
                acc[nt][q * 2] = x0; acc[nt][q * 2 + 1] = x1;
                sA[q] += x0 + x1;
                sB[q] += x0 * x0 + x1 * x1;
            }
        }
        #pragma unroll
        for (int q = 0; q < 4; q++) {
            sA[q] += __shfl_xor_sync(0xffffffffu, sA[q], 1);
            sA[q] += __shfl_xor_sync(0xffffffffu, sA[q], 2);
            sB[q] += __shfl_xor_sync(0xffffffffu, sB[q], 1);
            sB[q] += __shfl_xor_sync(0xffffffffu, sB[q], 2);
        }
        if (tig == 0) {
            #pragma unroll
            for (int q = 0; q < 4; q++) {
                int row = rowbase + q * 8 + gid;
                spar[colq * 128 + row]       = sA[q];
                spar[512 + colq * 128 + row] = sB[q];
            }
        }
        __syncthreads();
        float mV = 0.f, rV = 0.f;
        if (tid < 128) {
            float ss  = spar[tid] + spar[128 + tid] + spar[256 + tid] + spar[384 + tid];
            float ss2 = spar[512 + tid] + spar[640 + tid] + spar[768 + tid] + spar[896 + tid];
            mV = ss * (1.f / H);
            rV = rsqrtf(ss2 * (1.f / H) - mV * mV + 1e-5f);
        }
        __syncthreads();
        if (tid < 128) { spar[tid] = mV; spar[128 + tid] = rV; }
        __syncthreads();
        #pragma unroll
        for (int nt = 0; nt < 4; nt++) {
            int col = colq * 32 + nt * 8 + 2 * tig;
            float g0 = sg[col], g1 = sg[col + 1];
            float e0 = sbe[col], e1 = sbe[col + 1];
            #pragma unroll
            for (int q = 0; q < 4; q++) {
                int row = rowbase + q * 8 + gid;
                float m = spar[row], rs = spar[128 + row];
                float2 y;
                y.x = g0 * (acc[nt][q * 2]     - m) * rs + e0;
                y.y = g1 * (acc[nt][q * 2 + 1] - m) * rs + e1;
                *(float2*)(outE + (size_t)(grow0 + row) * H + col) = y;
            }
        }
    }
}

// ---------------- fp32 helpers for pre / ffn ----------------
template<int ROWS, int K4>
__device__ __forceinline__ void gemm_acc(float* acc, const float* A,
                                         const float* __restrict__ W,
                                         int n, int ldw) {
    const float4* A4 = reinterpret_cast<const float4*>(A);
    #pragma unroll 1
    for (int k4 = 0; k4 < K4; k4++) {
        const float* wp = W + (k4 * 4) * ldw + n;
        float w0 = wp[0], w1 = wp[ldw], w2 = wp[2 * ldw], w3 = wp[3 * ldw];
        #pragma unroll
        for (int rr = 0; rr < ROWS; rr++) {
            float4 a = A4[rr * K4 + k4];
            acc[rr] = fmaf(a.x, w0, acc[rr]);
            acc[rr] = fmaf(a.y, w1, acc[rr]);
            acc[rr] = fmaf(a.z, w2, acc[rr]);
            acc[rr] = fmaf(a.w, w3, acc[rr]);
        }
    }
}

__global__ void __launch_bounds__(128) k_pre(const float* __restrict__ hV,
                                             const float* __restrict__ W1,
                                             const float* __restrict__ b1,
                                             int ntok) {
    for (int i = blockIdx.x * 128 + threadIdx.x; i < ntok * H; i += gridDim.x * 128)
        g_dh[i] = 0.f;
    extern __shared__ float smf[];
    float* w1a = smf;
    float* w1c = smf + H * H;
    float* rows = smf + 2 * H * H;
    int tid = threadIdx.x;
    for (int i = tid; i < H * H; i += 128) {
        w1a[i] = W1[i];
        w1c[i] = W1[2 * H * H + i];
    }
    int t0 = blockIdx.x * 32;
    for (int i = tid; i < 32 * H; i += 128) rows[i] = hV[(size_t)t0 * H + i];
    __syncthreads();
    float bn = b1[tid];
    for (int rr = 0; rr < 32; rr++) {
        float a1 = bn, a3 = 0.f;
        const float4* rv = reinterpret_cast<const float4*>(rows + rr * H);
        #pragma unroll 8
        for (int k4 = 0; k4 < 32; k4++) {
            float4 v = rv[k4];
            int k = k4 * 4;
            a1 = fmaf(v.x, w1a[(k+0)*H+tid], a1); a1 = fmaf(v.y, w1a[(k+1)*H+tid], a1);
            a1 = fmaf(v.z, w1a[(k+2)*H+tid], a1); a1 = fmaf(v.w, w1a[(k+3)*H+tid], a1);
            a3 = fmaf(v.x, w1c[(k+0)*H+tid], a3); a3 = fmaf(v.y, w1c[(k+1)*H+tid], a3);
            a3 = fmaf(v.z, w1c[(k+2)*H+tid], a3); a3 = fmaf(v.w, w1c[(k+3)*H+tid], a3);
        }
        g_P1[(size_t)(t0+rr)*H+tid] = a1;
        g_P3[(size_t)(t0+rr)*H+tid] = a3;
    }
}

// FFN with fused LN1 at head (reads hV + g_dh directly)
__global__ void __launch_bounds__(256, 1) k_ffn(
    const float* __restrict__ hV,    const float* __restrict__ maskV,
    const float* __restrict__ g1,    const float* __restrict__ be1,
    const float* __restrict__ W_in,  const float* __restrict__ b_in,
    const float* __restrict__ W_out, const float* __restrict__ b_out,
    const float* __restrict__ g2,    const float* __restrict__ be2,
    const float* __restrict__ W11,   const float* __restrict__ b11,
    float* __restrict__ outV) {
    extern __shared__ float smf[];
    float* sX   = smf;               // 32*H
    float* sHid = smf + 32 * H;      // 32*512
    float* sMk  = sHid + 32 * 512;   // 32
    int tid = threadIdx.x;
    int t0 = blockIdx.x * 32;
    int half = tid >> 7, col = tid & 127;
    int warp = tid >> 5, lane = tid & 31;

    // LN1 fused: x = hV + g_dh/30, per-row LN -> sX
    for (int rr = warp; rr < 32; rr += 8) {
        size_t base = (size_t)(t0 + rr) * H;
        float v[4];
        #pragma unroll
        for (int j = 0; j < 4; j++) {
            int n = lane + 32 * j;
            v[j] = hV[base + n] + g_dh[base + n] * (1.f / 30.f);
        }
        float s = v[0]+v[1]+v[2]+v[3];
        float s2 = v[0]*v[0]+v[1]*v[1]+v[2]*v[2]+v[3]*v[3];
        #pragma unroll
        for (int o = 16; o; o >>= 1) {
            s  += __shfl_xor_sync(0xffffffffu, s,  o);
            s2 += __shfl_xor_sync(0xffffffffu, s2, o);
        }
        float m = s * (1.f/H);
        float rs = rsqrtf(s2 * (1.f/H) - m*m + 1e-5f);
        #pragma unroll
        for (int j = 0; j < 4; j++) {
            int n = lane + 32 * j;
            sX[rr * H + n] = g1[n] * (v[j] - m) * rs + be1[n];
        }
    }
    if (tid < 32) sMk[tid] = maskV[t0 + tid];
    __syncthreads();

    for (int cc = 0; cc < 2; cc++) {
        int c = cc * 256 + tid;
        float acc[32];
        float bi = b_in[c];
        #pragma unroll
        for (int rr = 0; rr < 32; rr++) acc[rr] = bi;
        gemm_acc<32, 32>(acc, sX, W_in, c, 512);
        #pragma unroll
        for (int rr = 0; rr < 32; rr++) sHid[rr * 512 + c] = gelu_f(acc[rr]);
    }
    __syncthreads();

    {
        float acc[16];
        float bo = b_out[col];
        #pragma unroll
        for (int rr = 0; rr < 16; rr++) acc[rr] = bo;
        gemm_acc<16, 128>(acc, sHid + half * 16 * 512, W_out, col, H);
        #pragma unroll
        for (int rr = 0; rr < 16; rr++)
            acc[rr] += sX[(half * 16 + rr) * H + col];
        __syncthreads();
        #pragma unroll
        for (int rr = 0; rr < 16; rr++)
            sHid[(half * 16 + rr) * H + col] = acc[rr];
    }
    __syncthreads();

    for (int rr = warp; rr < 32; rr += 8) {
        const float* row = sHid + rr * H;
        float v[4] = { row[lane], row[lane+32], row[lane+64], row[lane+96] };
        float s = v[0]+v[1]+v[2]+v[3];
        float s2 = v[0]*v[0]+v[1]*v[1]+v[2]*v[2]+v[3]*v[3];
        #pragma unroll
        for (int o = 16; o; o >>= 1) {
            s  += __shfl_xor_sync(0xffffffffu, s,  o);
            s2 += __shfl_xor_sync(0xffffffffu, s2, o);
        }
        float m = s * (1.f/H);
        float rs = rsqrtf(s2 * (1.f/H) - m*m + 1e-5f);
        float mk = sMk[rr];
        #pragma unroll
        for (int j = 0; j < 4; j++) {
            int n = lane + 32*j;
            float y = mk * (g2[n]*(v[j]-m)*rs + be2[n]);
            outV[(size_t)(t0+rr)*H + n] = y;
            sX[rr*H + n] = y;
        }
    }
    __syncthreads();

    {
        float acc2[16];
        float bb = b11[col];
        #pragma unroll
        for (int rr = 0; rr < 16; rr++) acc2[rr] = bb;
        gemm_acc<16, 32>(acc2, sX + half * 16 * H, W11, col, H);
        #pragma unroll
        for (int rr = 0; rr < 16; rr++)
            g_P11[(size_t)(t0 + half * 16 + rr) * H + col] = acc2[rr];
        #pragma unroll
        for (int rr = 0; rr < 16; rr++) acc2[rr] = 0.f;
        gemm_acc<16, 32>(acc2, sX + half * 16 * H, W11 + 2 * H * H, col, H);
        #pragma unroll
        for (int rr = 0; rr < 16; rr++)
            g_P13[(size_t)(t0 + half * 16 + rr) * H + col] = acc2[rr];
    }
}

// ---------------------------------------------------------------------------
extern "C" void kernel_launch(void* const* d_in, const int* in_sizes, int n_in,
                              void* d_out, int out_size) {
    const float* hV    = (const float*)d_in[0];
    const float* hE    = (const float*)d_in[1];
    const int*   Eidx  = (const int*)  d_in[2];
    const float* maskV = (const float*)d_in[3];
    const float* matt  = (const float*)d_in[4];
    const float* W1    = (const float*)d_in[5];
    const float* b1    = (const float*)d_in[6];
    const float* W2    = (const float*)d_in[7];
    const float* b2    = (const float*)d_in[8];
    const float* W3    = (const float*)d_in[9];
    const float* b3    = (const float*)d_in[10];
    const float* W11   = (const float*)d_in[11];
    const float* b11   = (const float*)d_in[12];
    const float* W12   = (const float*)d_in[13];
    const float* b12   = (const float*)d_in[14];
    const float* W13   = (const float*)d_in[15];
    const float* b13   = (const float*)d_in[16];
    const float* g1    = (const float*)d_in[17];
    const float* be1   = (const float*)d_in[18];
    const float* g2    = (const float*)d_in[19];
    const float* be2   = (const float*)d_in[20];
    const float* g3    = (const float*)d_in[21];
    const float* be3   = (const float*)d_in[22];
    const float* W_in  = (const float*)d_in[23];
    const float* b_in  = (const float*)d_in[24];
    const float* W_out = (const float*)d_in[25];
    const float* b_out = (const float*)d_in[26];

    int ntok = in_sizes[3];

    size_t smemP = (size_t)(2 * H * H + 32 * H) * sizeof(float);
    size_t smemB = (size_t)(32 * H + 32 * 512 + 64) * sizeof(float);

    cudaFuncSetAttribute(k_pre,    cudaFuncAttributeMaxDynamicSharedMemorySize, (int)smemP);
    cudaFuncSetAttribute(k_ffn,    cudaFuncAttributeMaxDynamicSharedMemorySize, (int)smemB);
    cudaFuncSetAttribute(k_mlp<0>, cudaFuncAttributeMaxDynamicSharedMemorySize, SMEM_MLP);
    cudaFuncSetAttribute(k_mlp<1>, cudaFuncAttributeMaxDynamicSharedMemorySize, SMEM_MLP);

    float* outV = (float*)d_out;
    float* outE = outV + (size_t)ntok * H;
    int ntile = ntok * KNB / 128;

    k_wprep<<< 6 * 16384 / 256, 256 >>>(W1 + H * H, W2, W3, W11 + H * H, W12, W13);
    k_pre  <<< ntok / 32, 128, smemP >>>(hV, W1, b1, ntok);
    k_mlp<0><<< ntile, 512, SMEM_MLP >>>(hE, Eidx, b2, b3, g1, be1, matt, outE);
    k_ffn  <<< ntok / 32, 256, smemB >>>(hV, maskV, g1, be1, W_in, b_in, W_out, b_out,
                                         g2, be2, W11, b11, outV);
    k_mlp<1><<< ntile, 512, SMEM_MLP >>>(hE, Eidx, b12, b13, g3, be3, matt, outE);
}

// round 9
// speedup vs baseline: 2.5320x; 1.0018x over previous
#include <cuda_runtime.h>
#include <cuda_fp16.h>
#include <math.h>
#include <cstdint>

#define H    128
#define KNB  48
#define LSEQ 2048
#define NTOK_MAX 4096

// ---------------- device scratch ----------------
__device__ float g_P1 [NTOK_MAX * H];
__device__ float g_P3 [NTOK_MAX * H];
__device__ float g_P11[NTOK_MAX * H];
__device__ float g_P13[NTOK_MAX * H];
__device__ float g_dh [NTOK_MAX * H];
// 6 weight mats, transposed [n][k], fp16 hi then fp16 lo (each 16384)
__device__ __half g_W[6 * 32768];

__device__ __forceinline__ float gelu_f(float x) {
    return 0.5f * x * (1.0f + erff(x * 0.70710678118654752f));
}

__device__ __forceinline__ uint32_t smem_u32(const void* p) {
    uint32_t a;
    asm("{ .reg .u64 t; cvta.to.shared.u64 t, %1; cvt.u32.u64 %0, t; }" : "=r"(a) : "l"(p));
    return a;
}

__device__ __forceinline__ void mma16816(float* c, const uint32_t* a,
                                         uint32_t b0, uint32_t b1) {
    asm volatile(
        "mma.sync.aligned.m16n8k16.row.col.f32.f16.f16.f32 "
        "{%0,%1,%2,%3}, {%4,%5,%6,%7}, {%8,%9}, {%0,%1,%2,%3};"
        : "+f"(c[0]), "+f"(c[1]), "+f"(c[2]), "+f"(c[3])
        : "r"(a[0]), "r"(a[1]), "r"(a[2]), "r"(a[3]), "r"(b0), "r"(b1));
}

#define LDSM4(r0, r1, r2, r3, addr) \
    asm volatile("ldmatrix.sync.aligned.m8n8.x4.shared.b16 {%0,%1,%2,%3}, [%4];" \
                 : "=r"(r0), "=r"(r1), "=r"(r2), "=r"(r3) : "r"(addr))

#define CP_COMMIT() asm volatile("cp.async.commit_group;" ::: "memory")
#define CP_WAIT0()  asm volatile("cp.async.wait_group 0;" ::: "memory")

// ---------------- smem layout (bytes) ----------------
#define LDA    136
#define STG_LD 130
#define SLAB  34816          // 128*136*2
#define SM_W0   0            // weight buf 0: hi slab + lo slab (69632)
#define SM_W1   69632        // weight buf 1 (also MODE0 staging late)
#define SM_A    139264       // activations: SINGLE fp16 slab (34816)
#define SM_NBR  174080       // 128 int
#define SM_MASK 174592       // 128 f
#define SM_B2   175104
#define SM_B3   175616
#define SM_G    176128
#define SM_BE   176640
#define SM_PAR  177152       // 1024 f = 4096
#define SMEM_MLP 181248

// ---------------- weight prep: transpose + fp16 hi/lo split ----------------
__global__ void k_wprep(const float* W1b, const float* W2, const float* W3,
                        const float* W11b, const float* W12, const float* W13) {
    int id = blockIdx.x * 256 + threadIdx.x;    // 6*16384
    int m = id >> 14, e = id & 16383;
    int n = e >> 7, k = e & 127;
    const float* srcs[6] = {W1b, W2, W3, W11b, W12, W13};
    float v = srcs[m][k * H + n];
    __half h = __float2half_rn(v);
    g_W[m * 32768 + e]         = h;
    g_W[m * 32768 + 16384 + e] = __float2half_rn(v - __half2float(h));
}

// async weight load (512 threads): 4096 x 16B
__device__ __forceinline__ void load_w_async(uint32_t smDst, int tid, int mat) {
    const char* src = (const char*)(g_W + (size_t)mat * 32768);
    #pragma unroll
    for (int it = 0; it < 8; it++) {
        int id = tid + it * 512;
        int hl = id >> 11, j = id & 2047;
        int n = j >> 4, kc = (j & 15) << 3;
        uint32_t dst = smDst + hl * SLAB + (uint32_t)((n * LDA + kc) * 2);
        asm volatile("cp.async.cg.shared.global [%0], [%1], 16;"
                     :: "r"(dst), "l"(src + (size_t)id * 16));
    }
}

// 2-pass GEMM (A fp16, W hi+lo): acc[4][8] += A(128x128) x W^T (warp: 32x32)
__device__ __forceinline__ void do_gemm(uint32_t wBase, uint32_t aBase, float acc[4][8],
                                        int rowbase, int colq, int lane) {
    int arow = rowbase + (lane & 15);
    int acol = (lane >> 4) << 3;
    uint32_t aOff = aBase + (uint32_t)((arow * LDA + acol) * 2);
    int nrow = colq * 32 + (lane & 7) + ((lane >> 4) << 3);
    int bcol = ((lane >> 3) & 1) << 3;
    uint32_t bOff = wBase + (uint32_t)((nrow * LDA + bcol) * 2);
    #pragma unroll 1
    for (int pass = 0; pass < 2; pass++) {
        uint32_t bB = bOff + ((pass == 1) ? SLAB : 0);
        #pragma unroll 1
        for (int ks = 0; ks < 8; ks++) {
            uint32_t a0[4], a1[4];
            LDSM4(a0[0], a0[1], a0[2], a0[3], aOff + ks * 32);
            LDSM4(a1[0], a1[1], a1[2], a1[3], aOff + 16 * LDA * 2 + ks * 32);
            #pragma unroll
            for (int ntp = 0; ntp < 2; ntp++) {
                uint32_t b0, b1, b2, b3;
                LDSM4(b0, b1, b2, b3, bB + ntp * 16 * LDA * 2 + ks * 32);
                mma16816(&acc[2 * ntp][0],     a0, b0, b1);
                mma16816(&acc[2 * ntp][4],     a1, b0, b1);
                mma16816(&acc[2 * ntp + 1][0], a0, b2, b3);
                mma16816(&acc[2 * ntp + 1][4], a1, b2, b3);
            }
        }
    }
}

// GELU(acc) -> A slab (fp16), for next layer's input
__device__ __forceinline__ void epi_act(char* sm, float acc[4][8],
                                        int rowbase, int colq, int gid, int tig) {
    #pragma unroll
    for (int nt = 0; nt < 4; nt++) {
        int col = colq * 32 + nt * 8 + 2 * tig;
        #pragma unroll
        for (int q = 0; q < 4; q++) {
            int row = rowbase + q * 8 + gid;
            __half2 h = __floats2half2_rn(gelu_f(acc[nt][q * 2]),
                                          gelu_f(acc[nt][q * 2 + 1]));
            *(uint32_t*)(sm + SM_A + (row * LDA + col) * 2) =
                *reinterpret_cast<uint32_t*>(&h);
        }
    }
}

// ---------------- fused 3-layer MLP over one 128-row tile (512 thr) ----------
// MODE 0: node messages -> masked per-token sums into g_dh (atomic)
// MODE 1: edge update -> +hE residual, row LN, write outE
template <int MODE>
__global__ void __launch_bounds__(512, 1) k_mlp(
    const float* __restrict__ hE, const int* __restrict__ Eidx,
    const float* __restrict__ bias2, const float* __restrict__ bias3,
    const float* __restrict__ lng, const float* __restrict__ lnb,
    const float* __restrict__ mattend, float* __restrict__ outE) {
    extern __shared__ char sm[];
    int*   snbr  = (int*)(sm + SM_NBR);
    float* smask = (float*)(sm + SM_MASK);
    float* sb2   = (float*)(sm + SM_B2);
    float* sb3   = (float*)(sm + SM_B3);
    float* sg    = (float*)(sm + SM_G);
    float* sbe   = (float*)(sm + SM_BE);
    float* spar  = (float*)(sm + SM_PAR);

    int tid = threadIdx.x, wid = tid >> 5, lane = tid & 31;
    int gid = lane >> 2, tig = lane & 3;
    int rowbase = (wid & 3) * 32;
    int colq = wid >> 2;
    int grow0 = blockIdx.x * 128;
    uint32_t smb = smem_u32(sm);

    load_w_async(smb + SM_W0, tid, MODE * 3 + 0);
    CP_COMMIT();

    if (tid < 128) {
        int gr = grow0 + tid;
        int t = gr / KNB;
        snbr[tid] = (t / LSEQ) * LSEQ + Eidx[gr];
        smask[tid] = (MODE == 0) ? mattend[gr] : 0.f;
        sb2[tid] = bias2[tid]; sb3[tid] = bias3[tid];
        sg[tid] = lng[tid];    sbe[tid] = lnb[tid];
    }

    // A <- fp16(hE tile)
    const float4* hE4 = reinterpret_cast<const float4*>(hE + (size_t)grow0 * H);
    #pragma unroll
    for (int it = 0; it < 8; it++) {
        int id = tid + it * 512;
        int rr = id >> 5, c4 = id & 31;
        float4 v = hE4[rr * 32 + c4];
        __half2 h01 = __floats2half2_rn(v.x, v.y);
        __half2 h23 = __floats2half2_rn(v.z, v.w);
        *(uint2*)(sm + SM_A + (rr * LDA + c4 * 4) * 2) =
            make_uint2(*reinterpret_cast<uint32_t*>(&h01),
                       *reinterpret_cast<uint32_t*>(&h23));
    }
    CP_WAIT0();
    __syncthreads();

    float acc[4][8];

    // ---- layer 1: acc init = P_center + P_nbr (exact fp32, from global) ----
    {
        const float* Padd = (MODE == 0) ? g_P1 : g_P11;
        const float* Pnbr = (MODE == 0) ? g_P3 : g_P13;
        int tokv[4], nbv[4];
        #pragma unroll
        for (int q = 0; q < 4; q++) {
            int row = rowbase + q * 8 + gid;
            tokv[q] = (grow0 + row) / KNB;
            nbv[q] = snbr[row];
        }
        #pragma unroll
        for (int nt = 0; nt < 4; nt++) {
            int col = colq * 32 + nt * 8 + 2 * tig;
            #pragma unroll
            for (int q = 0; q < 4; q++) {
                float2 a = *(const float2*)(Padd + (size_t)tokv[q] * H + col);
                float2 b = *(const float2*)(Pnbr + (size_t)nbv[q] * H + col);
                acc[nt][q * 2] = a.x + b.x; acc[nt][q * 2 + 1] = a.y + b.y;
            }
        }
    }
    load_w_async(smb + SM_W1, tid, MODE * 3 + 1);
    CP_COMMIT();
    do_gemm(smb + SM_W0, smb + SM_A, acc, rowbase, colq, lane);
    CP_WAIT0();
    __syncthreads();
    epi_act(sm, acc, rowbase, colq, gid, tig);
    __syncthreads();

    // ---- layer 2 ----
    #pragma unroll
    for (int nt = 0; nt < 4; nt++) {
        int col = colq * 32 + nt * 8 + 2 * tig;
        float b0 = sb2[col], b1 = sb2[col + 1];
        #pragma unroll
        for (int q = 0; q < 4; q++) { acc[nt][q * 2] = b0; acc[nt][q * 2 + 1] = b1; }
    }
    load_w_async(smb + SM_W0, tid, MODE * 3 + 2);
    CP_COMMIT();
    do_gemm(smb + SM_W1, smb + SM_A, acc, rowbase, colq, lane);
    CP_WAIT0();
    __syncthreads();
    epi_act(sm, acc, rowbase, colq, gid, tig);
    __syncthreads();

    // ---- layer 3 ----
    #pragma unroll
    for (int nt = 0; nt < 4; nt++) {
        int col = colq * 32 + nt * 8 + 2 * tig;
        float b0 = sb3[col], b1 = sb3[col + 1];
        #pragma unroll
        for (int q = 0; q < 4; q++) { acc[nt][q * 2] = b0; acc[nt][q * 2 + 1] = b1; }
    }
    do_gemm(smb + SM_W0, smb + SM_A, acc, rowbase, colq, lane);

    if (MODE == 0) {
        // masked values -> W1 region (dead), then per-token column sums
        __syncthreads();
        float* fA = (float*)(sm + SM_W1);
        #pragma unroll
        for (int nt = 0; nt < 4; nt++) {
            int col = colq * 32 + nt * 8 + 2 * tig;
            #pragma unroll
            for (int q = 0; q < 4; q++) {
                int row = rowbase + q * 8 + gid;
                float mk = smask[row];
                *(float2*)(fA + row * STG_LD + col) =
                    make_float2(mk * acc[nt][q * 2], mk * acc[nt][q * 2 + 1]);
            }
        }
        __syncthreads();
        int c = tid & 127, qtr = tid >> 7;
        int t0 = grow0 / KNB;
        for (int tok = t0 + qtr; KNB * tok < grow0 + 128; tok += 4) {
            int r0 = KNB * tok - grow0, r1 = r0 + KNB;
            if (r0 < 0) r0 = 0;
            if (r1 > 128) r1 = 128;
            float s = 0.f;
            for (int rr = r0; rr < r1; rr++) s += fA[rr * STG_LD + c];
            atomicAdd(&g_dh[(size_t)tok * H + c], s);
        }
    } else {
        // residual + per-row LN -> outE
        float sA[4], sB[4];
        #pragma unroll
        for (int q = 0; q < 4; q++) { sA[q] = 0.f; sB[q] = 0.f; }
        #pragma unroll
        for (int nt = 0; nt < 4; nt++) {
            int col = colq * 32 + nt * 8 + 2 * tig;
            #pragma unroll
            for (int q = 0; q < 4; q++) {
                int row = rowbase + q * 8 + gid;
                float2 res = *(const float2*)(hE + (size_t)(grow0 + row) * H + col);
                float x0 = acc[nt][q * 2]     + res.x;
                float x1 = acc[nt][q * 2 + 1] + res.y;
                acc[nt][q * 2] = x0; acc[nt][q * 2 + 1] = x1;
                sA[q] += x0 + x1;
                sB[q] += x0 * x0 + x1 * x1;
            }
        }
        #pragma unroll
        for (int q = 0; q < 4; q++) {
            sA[q] += __shfl_xor_sync(0xffffffffu, sA[q], 1);
            sA[q] += __shfl_xor_sync(0xffffffffu, sA[q], 2);
            sB[q] += __shfl_xor_sync(0xffffffffu, sB[q], 1);
            sB[q] += __shfl_xor_sync(0xffffffffu, sB[q], 2);
        }
        if (tig == 0) {
            #pragma unroll
            for (int q = 0; q < 4; q++) {
                int row = rowbase + q * 8 + gid;
                spar[colq * 128 + row]       = sA[q];
                spar[512 + colq * 128 + row] = sB[q];
            }
        }
        __syncthreads();
        float mV = 0.f, rV = 0.f;
        if (tid < 128) {
            float ss  = spar[tid] + spar[128 + tid] + spar[256 + tid] + spar[384 + tid];
            float ss2 = spar[512 + tid] + spar[640 + tid] + spar[768 + tid] + spar[896 + tid];
            mV = ss * (1.f / H);
            rV = rsqrtf(ss2 * (1.f / H) - mV * mV + 1e-5f);
        }
        __syncthreads();
        if (tid < 128) { spar[tid] = mV; spar[128 + tid] = rV; }
        __syncthreads();
        #pragma unroll
        for (int nt = 0; nt < 4; nt++) {
            int col = colq * 32 + nt * 8 + 2 * tig;
            float g0 = sg[col], g1 = sg[col + 1];
            float e0 = sbe[col], e1 = sbe[col + 1];
            #pragma unroll
            for (int q = 0; q < 4; q++) {
                int row = rowbase + q * 8 + gid;
                float m = spar[row], rs = spar[128 + row];
                float2 y;
                y.x = g0 * (acc[nt][q * 2]     - m) * rs + e0;
                y.y = g1 * (acc[nt][q * 2 + 1] - m) * rs + e1;
                *(float2*)(outE + (size_t)(grow0 + row) * H + col) = y;
            }
        }
    }
}

// ---------------- fp32 helpers for pre / ffn ----------------
template<int ROWS, int K4>
__device__ __forceinline__ void gemm_acc(float* acc, const float* A,
                                         const float* __restrict__ W,
                                         int n, int ldw) {
    const float4* A4 = reinterpret_cast<const float4*>(A);
    #pragma unroll 1
    for (int k4 = 0; k4 < K4; k4++) {
        const float* wp = W + (k4 * 4) * ldw + n;
        float w0 = wp[0], w1 = wp[ldw], w2 = wp[2 * ldw], w3 = wp[3 * ldw];
        #pragma unroll
        for (int rr = 0; rr < ROWS; rr++) {
            float4 a = A4[rr * K4 + k4];
            acc[rr] = fmaf(a.x, w0, acc[rr]);
            acc[rr] = fmaf(a.y, w1, acc[rr]);
            acc[rr] = fmaf(a.z, w2, acc[rr]);
            acc[rr] = fmaf(a.w, w3, acc[rr]);
        }
    }
}

__global__ void __launch_bounds__(128) k_pre(const float* __restrict__ hV,
                                             const float* __restrict__ W1,
                                             const float* __restrict__ b1,
                                             int ntok) {
    for (int i = blockIdx.x * 128 + threadIdx.x; i < ntok * H; i += gridDim.x * 128)
        g_dh[i] = 0.f;
    extern __shared__ float smf[];
    float* w1a = smf;
    float* w1c = smf + H * H;
    float* rows = smf + 2 * H * H;
    int tid = threadIdx.x;
    for (int i = tid; i < H * H; i += 128) {
        w1a[i] = W1[i];
        w1c[i] = W1[2 * H * H + i];
    }
    int t0 = blockIdx.x * 32;
    for (int i = tid; i < 32 * H; i += 128) rows[i] = hV[(size_t)t0 * H + i];
    __syncthreads();
    float bn = b1[tid];
    for (int rr = 0; rr < 32; rr++) {
        float a1 = bn, a3 = 0.f;
        const float4* rv = reinterpret_cast<const float4*>(rows + rr * H);
        #pragma unroll 8
        for (int k4 = 0; k4 < 32; k4++) {
            float4 v = rv[k4];
            int k = k4 * 4;
            a1 = fmaf(v.x, w1a[(k+0)*H+tid], a1); a1 = fmaf(v.y, w1a[(k+1)*H+tid], a1);
            a1 = fmaf(v.z, w1a[(k+2)*H+tid], a1); a1 = fmaf(v.w, w1a[(k+3)*H+tid], a1);
            a3 = fmaf(v.x, w1c[(k+0)*H+tid], a3); a3 = fmaf(v.y, w1c[(k+1)*H+tid], a3);
            a3 = fmaf(v.z, w1c[(k+2)*H+tid], a3); a3 = fmaf(v.w, w1c[(k+3)*H+tid], a3);
        }
        g_P1[(size_t)(t0+rr)*H+tid] = a1;
        g_P3[(size_t)(t0+rr)*H+tid] = a3;
    }
}

// FFN with fused LN1 at head (reads hV + g_dh directly)
__global__ void __launch_bounds__(256, 1) k_ffn(
    const float* __restrict__ hV,    const float* __restrict__ maskV,
    const float* __restrict__ g1,    const float* __restrict__ be1,
    const float* __restrict__ W_in,  const float* __restrict__ b_in,
    const float* __restrict__ W_out, const float* __restrict__ b_out,
    const float* __restrict__ g2,    const float* __restrict__ be2,
    const float* __restrict__ W11,   const float* __restrict__ b11,
    float* __restrict__ outV) {
    extern __shared__ float smf[];
    float* sX   = smf;               // 32*H
    float* sHid = smf + 32 * H;      // 32*512
    float* sMk  = sHid + 32 * 512;   // 32
    int tid = threadIdx.x;
    int t0 = blockIdx.x * 32;
    int half = tid >> 7, col = tid & 127;
    int warp = tid >> 5, lane = tid & 31;

    // LN1 fused: x = hV + g_dh/30, per-row LN -> sX
    for (int rr = warp; rr < 32; rr += 8) {
        size_t base = (size_t)(t0 + rr) * H;
        float v[4];
        #pragma unroll
        for (int j = 0; j < 4; j++) {
            int n = lane + 32 * j;
            v[j] = hV[base + n] + g_dh[base + n] * (1.f / 30.f);
        }
        float s = v[0]+v[1]+v[2]+v[3];
        float s2 = v[0]*v[0]+v[1]*v[1]+v[2]*v[2]+v[3]*v[3];
        #pragma unroll
        for (int o = 16; o; o >>= 1) {
            s  += __shfl_xor_sync(0xffffffffu, s,  o);
            s2 += __shfl_xor_sync(0xffffffffu, s2, o);
        }
        float m = s * (1.f/H);
        float rs = rsqrtf(s2 * (1.f/H) - m*m + 1e-5f);
        #pragma unroll
        for (int j = 0; j < 4; j++) {
            int n = lane + 32 * j;
            sX[rr * H + n] = g1[n] * (v[j] - m) * rs + be1[n];
        }
    }
    if (tid < 32) sMk[tid] = maskV[t0 + tid];
    __syncthreads();

    for (int cc = 0; cc < 2; cc++) {
        int c = cc * 256 + tid;
        float acc[32];
        float bi = b_in[c];
        #pragma unroll
        for (int rr = 0; rr < 32; rr++) acc[rr] = bi;
        gemm_acc<32, 32>(acc, sX, W_in, c, 512);
        #pragma unroll
        for (int rr = 0; rr < 32; rr++) sHid[rr * 512 + c] = gelu_f(acc[rr]);
    }
    __syncthreads();

    {
        float acc[16];
        float bo = b_out[col];
        #pragma unroll
        for (int rr = 0; rr < 16; rr++) acc[rr] = bo;
        gemm_acc<16, 128>(acc, sHid + half * 16 * 512, W_out, col, H);
        #pragma unroll
        for (int rr = 0; rr < 16; rr++)
            acc[rr] += sX[(half * 16 + rr) * H + col];
        __syncthreads();
        #pragma unroll
        for (int rr = 0; rr < 16; rr++)
            sHid[(half * 16 + rr) * H + col] = acc[rr];
    }
    __syncthreads();

    for (int rr = warp; rr < 32; rr += 8) {
        const float* row = sHid + rr * H;
        float v[4] = { row[lane], row[lane+32], row[lane+64], row[lane+96] };
        float s = v[0]+v[1]+v[2]+v[3];
        float s2 = v[0]*v[0]+v[1]*v[1]+v[2]*v[2]+v[3]*v[3];
        #pragma unroll
        for (int o = 16; o; o >>= 1) {
            s  += __shfl_xor_sync(0xffffffffu, s,  o);
            s2 += __shfl_xor_sync(0xffffffffu, s2, o);
        }
        float m = s * (1.f/H);
        float rs = rsqrtf(s2 * (1.f/H) - m*m + 1e-5f);
        float mk = sMk[rr];
        #pragma unroll
        for (int j = 0; j < 4; j++) {
            int n = lane + 32*j;
            float y = mk * (g2[n]*(v[j]-m)*rs + be2[n]);
            outV[(size_t)(t0+rr)*H + n] = y;
            sX[rr*H + n] = y;
        }
    }
    __syncthreads();

    {
        float acc2[16];
        float bb = b11[col];
        #pragma unroll
        for (int rr = 0; rr < 16; rr++) acc2[rr] = bb;
        gemm_acc<16, 32>(acc2, sX + half * 16 * H, W11, col, H);
        #pragma unroll
        for (int rr = 0; rr < 16; rr++)
            g_P11[(size_t)(t0 + half * 16 + rr) * H + col] = acc2[rr];
        #pragma unroll
        for (int rr = 0; rr < 16; rr++) acc2[rr] = 0.f;
        gemm_acc<16, 32>(acc2, sX + half * 16 * H, W11 + 2 * H * H, col, H);
        #pragma unroll
        for (int rr = 0; rr < 16; rr++)
            g_P13[(size_t)(t0 + half * 16 + rr) * H + col] = acc2[rr];
    }
}

// ---------------------------------------------------------------------------
extern "C" void kernel_launch(void* const* d_in, const int* in_sizes, int n_in,
                              void* d_out, int out_size) {
    const float* hV    = (const float*)d_in[0];
    const float* hE    = (const float*)d_in[1];
    const int*   Eidx  = (const int*)  d_in[2];
    const float* maskV = (const float*)d_in[3];
    const float* matt  = (const float*)d_in[4];
    const float* W1    = (const float*)d_in[5];
    const float* b1    = (const float*)d_in[6];
    const float* W2    = (const float*)d_in[7];
    const float* b2    = (const float*)d_in[8];
    const float* W3    = (const float*)d_in[9];
    const float* b3    = (const float*)d_in[10];
    const float* W11   = (const float*)d_in[11];
    const float* b11   = (const float*)d_in[12];
    const float* W12   = (const float*)d_in[13];
    const float* b12   = (const float*)d_in[14];
    const float* W13   = (const float*)d_in[15];
    const float* b13   = (const float*)d_in[16];
    const float* g1    = (const float*)d_in[17];
    const float* be1   = (const float*)d_in[18];
    const float* g2    = (const float*)d_in[19];
    const float* be2   = (const float*)d_in[20];
    const float* g3    = (const float*)d_in[21];
    const float* be3   = (const float*)d_in[22];
    const float* W_in  = (const float*)d_in[23];
    const float* b_in  = (const float*)d_in[24];
    const float* W_out = (const float*)d_in[25];
    const float* b_out = (const float*)d_in[26];

    int ntok = in_sizes[3];

    size_t smemP = (size_t)(2 * H * H + 32 * H) * sizeof(float);
    size_t smemB = (size_t)(32 * H + 32 * 512 + 64) * sizeof(float);

    cudaFuncSetAttribute(k_pre,    cudaFuncAttributeMaxDynamicSharedMemorySize, (int)smemP);
    cudaFuncSetAttribute(k_ffn,    cudaFuncAttributeMaxDynamicSharedMemorySize, (int)smemB);
    cudaFuncSetAttribute(k_mlp<0>, cudaFuncAttributeMaxDynamicSharedMemorySize, SMEM_MLP);
    cudaFuncSetAttribute(k_mlp<1>, cudaFuncAttributeMaxDynamicSharedMemorySize, SMEM_MLP);

    float* outV = (float*)d_out;
    float* outE = outV + (size_t)ntok * H;
    int ntile = ntok * KNB / 128;

    k_wprep<<< 6 * 16384 / 256, 256 >>>(W1 + H * H, W2, W3, W11 + H * H, W12, W13);
    k_pre  <<< ntok / 32, 128, smemP >>>(hV, W1, b1, ntok);
    k_mlp<0><<< ntile, 512, SMEM_MLP >>>(hE, Eidx, b2, b3, g1, be1, matt, outE);
    k_ffn  <<< ntok / 32, 256, smemB >>>(hV, maskV, g1, be1, W_in, b_in, W_out, b_out,
                                         g2, be2, W11, b11, outV);
    k_mlp<1><<< ntile, 512, SMEM_MLP >>>(hE, Eidx, b12, b13, g3, be3, matt, outE);
}